// round 14
// baseline (speedup 1.0000x reference)
#include <cuda_runtime.h>
#include <cuda_bf16.h>
#include <cstdint>

#define B_    8
#define L_    4096
#define DM_   512
#define H_    8
#define D_    64
#define BH_   64
#define KTOP_ 8
#define M_    (B_ * L_)   // 32768
#define WN_   (DM_ * DM_) // 262144

// ---------------- scratch (device globals; no allocations allowed) ----------
__device__ __nv_bfloat16 gx_h[M_ * DM_];   // x hi/lo, [M,512]
__device__ __nv_bfloat16 gx_l[M_ * DM_];
__device__ __nv_bfloat16 gw_h[4 * WN_];    // Wq,Wk,Wv,Wo hi/lo, each [512,512]
__device__ __nv_bfloat16 gw_l[4 * WN_];
__device__ __nv_bfloat16 gc_h[M_ * DM_];   // ctx hi/lo, [M,512]
__device__ __nv_bfloat16 gc_l[M_ * DM_];
__device__ float  g_q[BH_ * D_ * L_];      // [bh][d][l]  (transposed)
__device__ float  g_k[BH_ * D_ * L_];
__device__ float  g_v[BH_ * L_ * D_];      // [bh][l][d]
__device__ float2 g_P[BH_ * 8 * L_];
__device__ float  g_w[BH_ * KTOP_];
__device__ int    g_i[BH_ * KTOP_];

// ---------------- bf16 pack/split helpers ------------------------------------
__device__ __forceinline__ unsigned pack2(float x, float y) {
    unsigned d;
    asm("cvt.rn.bf16x2.f32 %0, %1, %2;" : "=r"(d) : "f"(y), "f"(x));
    return d;   // lo half = bf16(x), hi half = bf16(y)
}
__device__ __forceinline__ void split2(float x, float y, unsigned& h, unsigned& l) {
    h = pack2(x, y);
    float hx = __uint_as_float(h << 16);
    float hy = __uint_as_float(h & 0xFFFF0000u);
    l = pack2(x - hx, y - hy);
}

// ---------------- split kernels -----------------------------------------------
__global__ void __launch_bounds__(256) split_x_kernel(const float* __restrict__ src,
                                                      unsigned* __restrict__ hi,
                                                      unsigned* __restrict__ lo) {
    const int i = blockIdx.x * 256 + threadIdx.x;   // float4 index
    float4 v = ((const float4*)src)[i];
    unsigned h01, l01, h23, l23;
    split2(v.x, v.y, h01, l01);
    split2(v.z, v.w, h23, l23);
    ((uint2*)hi)[i] = make_uint2(h01, h23);
    ((uint2*)lo)[i] = make_uint2(l01, l23);
}

// grid (256, 4): blockIdx.y selects weight matrix
__global__ void __launch_bounds__(256) split_w_kernel(const float* __restrict__ Wq,
                                                      const float* __restrict__ Wk,
                                                      const float* __restrict__ Wv,
                                                      const float* __restrict__ Wo,
                                                      unsigned* __restrict__ hi,
                                                      unsigned* __restrict__ lo) {
    const int sel = blockIdx.y;
    const float* src = sel == 0 ? Wq : (sel == 1 ? Wk : (sel == 2 ? Wv : Wo));
    const int i = blockIdx.x * 256 + threadIdx.x;
    float4 v = ((const float4*)src)[i];
    unsigned h01, l01, h23, l23;
    split2(v.x, v.y, h01, l01);
    split2(v.z, v.w, h23, l23);
    const int o = sel * (WN_ / 4) + i;
    ((uint2*)hi)[o] = make_uint2(h01, h23);
    ((uint2*)lo)[o] = make_uint2(l01, l23);
}

// Swizzled byte offset inside one 4KB k-tile buffer (128 rows x 32B).
__device__ __forceinline__ int swad(int r, int hf) {
    const int line = r >> 2;
    const int chunk = (((r & 3) * 2 + hf) ^ (line & 1));
    return line * 128 + chunk * 16;
}

__device__ __forceinline__ void cp16s(uint32_t saddr, const void* g) {
    asm volatile("cp.async.cg.shared.global [%0], [%1], 16;" :: "r"(saddr), "l"(g));
}

#define LDSM4(R, a)                                                           \
    asm volatile("ldmatrix.sync.aligned.m8n8.x4.shared.b16 {%0,%1,%2,%3}, [%4];" \
                 : "=r"((R)[0]), "=r"((R)[1]), "=r"((R)[2]), "=r"((R)[3])     \
                 : "r"(a))

#define MMA16(C, Ar, B0r, B1r)                                                \
    asm volatile(                                                             \
        "mma.sync.aligned.m16n8k16.row.col.f32.bf16.bf16.f32 "                \
        "{%0,%1,%2,%3},{%4,%5,%6,%7},{%8,%9},{%0,%1,%2,%3};"                  \
        : "+f"((C)[0]), "+f"((C)[1]), "+f"((C)[2]), "+f"((C)[3])              \
        : "r"((Ar)[0]), "r"((Ar)[1]), "r"((Ar)[2]), "r"((Ar)[3]),             \
          "r"(B0r), "r"(B1r))

// ---------------- GEMM: C[m,n] = sum_k A[m,k]*W[n,k] + bias[n] ---------------
// Pre-split 3xBF16; 3-stage cp.async pipeline; ldmatrix; 64x64 warp tiles
// (4 warps, 2x2 grid; MMA:LDSM ratio 6).
// MODE 0: row-major [M,512]. MODE 1: [B,H,L,D]. MODE 2: [B,H,D,L].
// smem: Ah @0, Al @12288, Wh @24576, Wl @36864; each [3 stage][4KB swizzled]
template <int MODE>
__global__ void __launch_bounds__(128, 2) gemm512(const __nv_bfloat16* __restrict__ Ahp,
                                                  const __nv_bfloat16* __restrict__ Alp,
                                                  const __nv_bfloat16* __restrict__ Whp,
                                                  const __nv_bfloat16* __restrict__ Wlp,
                                                  const float* __restrict__ bias,
                                                  float* __restrict__ out) {
    __shared__ __align__(128) unsigned char gsm[49152];
    const uint32_t sb = (uint32_t)__cvta_generic_to_shared(gsm);

    const int tid  = threadIdx.x;
    const int bm   = blockIdx.x * 128;
    const int bn   = blockIdx.y * 128;
    const int warp = tid >> 5, lane = tid & 31;
    const int g  = lane >> 2, tg = lane & 3;
    const int wm = (warp >> 1) * 64;   // 2 warps along M
    const int wn = (warp & 1) * 64;    // 2 warps along N

    float c[4][8][4];
#pragma unroll
    for (int i = 0; i < 4; i++)
#pragma unroll
        for (int j = 0; j < 8; j++)
#pragma unroll
            for (int r = 0; r < 4; r++) c[i][j][r] = 0.f;

    // cp.async: thread t loads row t (both 16B halves) of each matrix-half
    const int cr = tid;                 // 0..127
    const int sw0 = swad(cr, 0), sw1 = swad(cr, 1);
    const __nv_bfloat16* srcA_h = Ahp + (size_t)(bm + cr) * 512;
    const __nv_bfloat16* srcA_l = Alp + (size_t)(bm + cr) * 512;
    const __nv_bfloat16* srcW_h = Whp + (size_t)(bn + cr) * 512;
    const __nv_bfloat16* srcW_l = Wlp + (size_t)(bn + cr) * 512;

    // ldmatrix per-lane addresses (relative to stage 0)
    const int lr = lane & 7, gI = lane >> 3;
    uint32_t aA[4], aW[4];
#pragma unroll
    for (int im = 0; im < 4; im++)
        aA[im] = sb + swad(wm + im * 16 + lr + (gI & 1) * 8, gI >> 1);
#pragma unroll
    for (int jp = 0; jp < 4; jp++)
        aW[jp] = sb + 24576 + swad(wn + jp * 16 + lr + ((gI >> 1) & 1) * 8, gI & 1);

    auto cp_tile = [&](int buf, int kt) {
        const int k0 = kt * 16;
        const uint32_t d = sb + buf * 4096;
        cp16s(d + sw0,         srcA_h + k0);
        cp16s(d + sw1,         srcA_h + k0 + 8);
        cp16s(d + 12288 + sw0, srcA_l + k0);
        cp16s(d + 12288 + sw1, srcA_l + k0 + 8);
        cp16s(d + 24576 + sw0, srcW_h + k0);
        cp16s(d + 24576 + sw1, srcW_h + k0 + 8);
        cp16s(d + 36864 + sw0, srcW_l + k0);
        cp16s(d + 36864 + sw1, srcW_l + k0 + 8);
        asm volatile("cp.async.commit_group;" ::: "memory");
    };

    auto compute = [&](int buf) {
        const uint32_t bo = buf * 4096;
        unsigned ah[4][4], al[4][4];
#pragma unroll
        for (int im = 0; im < 4; im++) LDSM4(ah[im], aA[im] + bo);
#pragma unroll
        for (int im = 0; im < 4; im++) LDSM4(al[im], aA[im] + 12288 + bo);
#pragma unroll
        for (int jp = 0; jp < 4; jp++) {
            unsigned wh[4], wl[4];
            LDSM4(wh, aW[jp] + bo);
            LDSM4(wl, aW[jp] + 12288 + bo);
            // pass 1 (hh): 8 independent accumulators
#pragma unroll
            for (int im = 0; im < 4; im++) {
                MMA16(c[im][2 * jp],     ah[im], wh[0], wh[1]);
                MMA16(c[im][2 * jp + 1], ah[im], wh[2], wh[3]);
            }
            // pass 2 (hl)
#pragma unroll
            for (int im = 0; im < 4; im++) {
                MMA16(c[im][2 * jp],     ah[im], wl[0], wl[1]);
                MMA16(c[im][2 * jp + 1], ah[im], wl[2], wl[3]);
            }
            // pass 3 (lh)
#pragma unroll
            for (int im = 0; im < 4; im++) {
                MMA16(c[im][2 * jp],     al[im], wh[0], wh[1]);
                MMA16(c[im][2 * jp + 1], al[im], wh[2], wh[3]);
            }
        }
    };

    cp_tile(0, 0);
    cp_tile(1, 1);
#pragma unroll 1
    for (int kt = 0; kt < 32; kt++) {
        const int buf = kt % 3;
        if (kt < 30) {
            asm volatile("cp.async.wait_group 1;" ::: "memory");
        } else {
            asm volatile("cp.async.wait_group 0;" ::: "memory");
        }
        __syncthreads();
        if (kt < 30) cp_tile((kt + 2) % 3, kt + 2);
        compute(buf);
    }

    // epilogue
#pragma unroll
    for (int im = 0; im < 4; im++) {
#pragma unroll
        for (int jn = 0; jn < 8; jn++) {
            const int mrow = bm + wm + im * 16 + g;
            const int ncol = bn + wn + jn * 8 + 2 * tg;
            const float bv0 = bias[ncol], bv1 = bias[ncol + 1];
            float v00 = c[im][jn][0] + bv0;
            float v01 = c[im][jn][1] + bv1;
            float v10 = c[im][jn][2] + bv0;
            float v11 = c[im][jn][3] + bv1;
            if (MODE == 0) {
                out[(size_t)mrow * 512 + ncol]           = v00;
                out[(size_t)mrow * 512 + ncol + 1]       = v01;
                out[(size_t)(mrow + 8) * 512 + ncol]     = v10;
                out[(size_t)(mrow + 8) * 512 + ncol + 1] = v11;
            } else if (MODE == 1) {
                const int h = ncol >> 6, d = ncol & 63;
                const int b = mrow >> 12, l = mrow & 4095;
                size_t base = (((size_t)(b * 8 + h)) * 4096 + l) * 64 + d;
                out[base]     = v00;
                out[base + 1] = v01;
                out[base + 8 * 64]     = v10;
                out[base + 8 * 64 + 1] = v11;
            } else {
                const int b = mrow >> 12, l = mrow & 4095;
                size_t base = ((size_t)(b * 512 + ncol)) * 4096 + l;
                out[base]        = v00;
                out[base + 4096] = v01;
                out[base + 8]        = v10;
                out[base + 4096 + 8] = v11;
            }
        }
    }
}

// ---------------- radix-8 Stockham FFT, 3 smem stages + register last stage ---
__device__ __forceinline__ float2 cmul(float2 a, float2 b) {
    return make_float2(a.x * b.x - a.y * b.y, a.x * b.y + a.y * b.x);
}
__device__ __forceinline__ float2 cadd(float2 a, float2 b) {
    return make_float2(a.x + b.x, a.y + b.y);
}
__device__ __forceinline__ float2 csub(float2 a, float2 b) {
    return make_float2(a.x - b.x, a.y - b.y);
}

__device__ __forceinline__ void bfly8(const float2* a, float2* z) {
    float2 t0 = cadd(a[0], a[4]), t1 = csub(a[0], a[4]);
    float2 t2 = cadd(a[2], a[6]), t3 = csub(a[2], a[6]);
    float2 E0 = cadd(t0, t2), E2 = csub(t0, t2);
    float2 E1 = make_float2(t1.x + t3.y, t1.y - t3.x);
    float2 E3 = make_float2(t1.x - t3.y, t1.y + t3.x);
    float2 u0 = cadd(a[1], a[5]), u1 = csub(a[1], a[5]);
    float2 u2 = cadd(a[3], a[7]), u3 = csub(a[3], a[7]);
    float2 O0 = cadd(u0, u2), O2 = csub(u0, u2);
    float2 O1 = make_float2(u1.x + u3.y, u1.y - u3.x);
    float2 O3 = make_float2(u1.x - u3.y, u1.y + u3.x);
    const float r = 0.70710678118654752f;
    float2 P1 = make_float2(r * (O1.x + O1.y), r * (O1.y - O1.x));
    float2 P2 = make_float2(O2.y, -O2.x);
    float2 P3 = make_float2(r * (O3.y - O3.x), -r * (O3.x + O3.y));
    z[0] = cadd(E0, O0); z[4] = csub(E0, O0);
    z[1] = cadd(E1, P1); z[5] = csub(E1, P1);
    z[2] = cadd(E2, P2); z[6] = csub(E2, P2);
    z[3] = cadd(E3, P3); z[7] = csub(E3, P3);
}

__device__ void fft4096r8_3(float2* x, float2* y, const float2* tw, int tid) {
    int ls = 0;
#pragma unroll 1
    for (int stage = 0; stage < 3; stage++) {
        const int s = 1 << ls;
        const int q = tid & (s - 1);
        const int sp = tid - q;
        float2 a[8], z[8];
#pragma unroll
        for (int j = 0; j < 8; j++) a[j] = x[tid + j * 512];
        bfly8(a, z);
        const int ob = 8 * tid - 7 * q;
        y[ob] = z[0];
#pragma unroll
        for (int j = 1; j < 8; j++) y[ob + j * s] = cmul(tw[j * sp], z[j]);
        __syncthreads();
        float2* tmp = x; x = y; y = tmp;
        ls += 3;
    }
}

__device__ __forceinline__ void fft_last(const float2* xin, float2* z, int tid) {
    float2 a[8];
#pragma unroll
    for (int j = 0; j < 8; j++) a[j] = xin[tid + j * 512];
    bfly8(a, z);
}

// ---------------- Phase A: packed FFT(q+ik), 8 d's per block, reduce ---------
__global__ void __launch_bounds__(512) fwd_corr_kernel() {
    extern __shared__ float2 sm[];
    float2* b0 = sm;
    float2* b1 = sm + 4096;
    float2* tw = sm + 8192;
    const int tid = threadIdx.x;
    for (int j = tid; j < 4096; j += 512) {
        float s, c;
        sincospif(-(float)j / 2048.0f, &s, &c);
        tw[j] = make_float2(c, s);
    }
    const int bh = blockIdx.x >> 3, grp = blockIdx.x & 7;
    const float* qb = g_q + ((size_t)bh * 64 + grp * 8) * 4096;
    const float* kb = g_k + ((size_t)bh * 64 + grp * 8) * 4096;

    float2 acc[8];
#pragma unroll
    for (int j = 0; j < 8; j++) acc[j] = make_float2(0.f, 0.f);

    for (int dd = 0; dd < 8; dd++) {
        const float* qp = qb + (size_t)dd * 4096;
        const float* kp = kb + (size_t)dd * 4096;
        __syncthreads();
#pragma unroll
        for (int j = 0; j < 8; j++) {
            int t = tid + j * 512;
            b0[t] = make_float2(qp[t], kp[t]);
        }
        __syncthreads();
        fft4096r8_3(b0, b1, tw, tid);
        float2 z[8];
        fft_last(b1, z, tid);
#pragma unroll
        for (int r = 0; r < 8; r++) b0[tid + r * 512] = z[r];
        __syncthreads();
#pragma unroll
        for (int j = 0; j < 8; j++) {
            const int f = tid + j * 512;
            float2 Z  = z[j];
            float2 Zm = b0[(4096 - f) & 4095];
            float Qr = 0.5f * (Z.x + Zm.x);
            float Qi = 0.5f * (Z.y - Zm.y);
            float Kr = 0.5f * (Z.y + Zm.y);
            float Ki = 0.5f * (Zm.x - Z.x);
            acc[j].x += Qr * Kr + Qi * Ki;
            acc[j].y += Qr * Ki - Qi * Kr;
        }
    }
    float2* Pout = g_P + (size_t)blockIdx.x * 4096;
#pragma unroll
    for (int j = 0; j < 8; j++) Pout[tid + j * 512] = acc[j];
}

// ---------------- Phase B fused: sum partials, FFT, top-8 + softmax ----------
__global__ void __launch_bounds__(512) inv_topk_kernel() {
    extern __shared__ float2 sm[];
    float2* b0 = sm;
    float2* b1 = sm + 4096;
    float2* tw = sm + 8192;
    const int tid = threadIdx.x;
    for (int j = tid; j < 4096; j += 512) {
        float s, c;
        sincospif(-(float)j / 2048.0f, &s, &c);
        tw[j] = make_float2(c, s);
    }
    const int bh = blockIdx.x;
    const float2* Pp = g_P + (size_t)bh * 8 * 4096;
    float2 acc[8];
#pragma unroll
    for (int j = 0; j < 8; j++) acc[j] = make_float2(0.f, 0.f);
    for (int grp = 0; grp < 8; grp++) {
#pragma unroll
        for (int j = 0; j < 8; j++) {
            float2 v = Pp[(size_t)grp * 4096 + tid + j * 512];
            acc[j].x += v.x;
            acc[j].y += v.y;
        }
    }
#pragma unroll
    for (int j = 0; j < 8; j++) b0[tid + j * 512] = acc[j];
    __syncthreads();
    fft4096r8_3(b0, b1, tw, tid);
    float2 z[8];
    fft_last(b1, z, tid);

    float* scr   = (float*)sm;
    float* svals = scr + 4096;
    int*   sidx  = (int*)(svals + 512);
    __shared__ int   chosen[KTOP_];
    __shared__ float chval[KTOP_];
    __syncthreads();
    const float sc = 1.0f / (4096.0f * 64.0f);
#pragma unroll
    for (int r = 0; r < 8; r++) scr[tid + r * 512] = z[r].x * sc;
    __syncthreads();

    for (int it = 0; it < KTOP_; it++) {
        float best = -3.0e38f;
        int bi = -1;
#pragma unroll
        for (int jj = 0; jj < 8; jj++) {
            const int t = tid + jj * 512;
            float v = scr[t];
            bool used = false;
            for (int u = 0; u < it; u++)
                if (chosen[u] == t) used = true;
            if (!used && (v > best || (v == best && t < bi))) { best = v; bi = t; }
        }
        svals[tid] = best;
        sidx[tid] = bi;
        __syncthreads();
        for (int off = 256; off > 0; off >>= 1) {
            if (tid < off) {
                if (svals[tid + off] > svals[tid] ||
                    (svals[tid + off] == svals[tid] && sidx[tid + off] < sidx[tid])) {
                    svals[tid] = svals[tid + off];
                    sidx[tid]  = sidx[tid + off];
                }
            }
            __syncthreads();
        }
        if (tid == 0) { chosen[it] = sidx[0]; chval[it] = svals[0]; }
        __syncthreads();
    }
    if (tid == 0) {
        float mx = chval[0];
        float e[KTOP_], se = 0.f;
        for (int u = 0; u < KTOP_; u++) { e[u] = expf(chval[u] - mx); se += e[u]; }
        float inv = 1.0f / se;
        for (int u = 0; u < KTOP_; u++) {
            g_w[bh * KTOP_ + u] = e[u] * inv;
            g_i[bh * KTOP_ + u] = chosen[u];
        }
    }
}

// ---------------- Phase D: gather V, write split bf16 ctx ---------------------
__global__ void __launch_bounds__(256) gather_kernel() {
    const int bh = blockIdx.y;
    const int b = bh >> 3, h = bh & 7;
    const int li = threadIdx.x >> 4;
    const int d4 = threadIdx.x & 15;
    const int l  = blockIdx.x * 16 + li;
    __shared__ float w[KTOP_];
    __shared__ int   ix[KTOP_];
    if (threadIdx.x < KTOP_) {
        w[threadIdx.x]  = g_w[bh * KTOP_ + threadIdx.x];
        ix[threadIdx.x] = g_i[bh * KTOP_ + threadIdx.x];
    }
    __syncthreads();
    const float4* vp = (const float4*)(g_v + (size_t)bh * L_ * D_);
    float4 acc = make_float4(0.f, 0.f, 0.f, 0.f);
#pragma unroll
    for (int u = 0; u < KTOP_; u++) {
        const int src = (l + ix[u]) & 4095;
        float4 v = vp[src * 16 + d4];
        const float wu = w[u];
        acc.x += wu * v.x;
        acc.y += wu * v.y;
        acc.z += wu * v.z;
        acc.w += wu * v.w;
    }
    unsigned h01, l01, h23, l23;
    split2(acc.x, acc.y, h01, l01);
    split2(acc.z, acc.w, h23, l23);
    const size_t e = (size_t)(b * L_ + l) * DM_ + h * 64 + d4 * 4;
    *(uint2*)((unsigned*)gc_h + (e >> 1)) = make_uint2(h01, h23);
    *(uint2*)((unsigned*)gc_l + (e >> 1)) = make_uint2(l01, l23);
}

// ---------------- launch ------------------------------------------------------
extern "C" void kernel_launch(void* const* d_in, const int* in_sizes, int n_in,
                              void* d_out, int out_size) {
    const float* x  = (const float*)d_in[0];
    const float* Wq = (const float*)d_in[1];
    const float* bq = (const float*)d_in[2];
    const float* Wk = (const float*)d_in[3];
    const float* bk = (const float*)d_in[4];
    const float* Wv = (const float*)d_in[5];
    const float* bv = (const float*)d_in[6];
    const float* Wo = (const float*)d_in[7];
    const float* bo = (const float*)d_in[8];
    float* out = (float*)d_out;

    float *qp, *kp, *vp;
    __nv_bfloat16 *xh, *xl, *wh, *wl, *ch, *cl;
    cudaGetSymbolAddress((void**)&qp, g_q);
    cudaGetSymbolAddress((void**)&kp, g_k);
    cudaGetSymbolAddress((void**)&vp, g_v);
    cudaGetSymbolAddress((void**)&xh, gx_h);
    cudaGetSymbolAddress((void**)&xl, gx_l);
    cudaGetSymbolAddress((void**)&wh, gw_h);
    cudaGetSymbolAddress((void**)&wl, gw_l);
    cudaGetSymbolAddress((void**)&ch, gc_h);
    cudaGetSymbolAddress((void**)&cl, gc_l);

    const int FFT_SMEM = 98304;
    cudaFuncSetAttribute(fwd_corr_kernel, cudaFuncAttributeMaxDynamicSharedMemorySize, FFT_SMEM);
    cudaFuncSetAttribute(inv_topk_kernel, cudaFuncAttributeMaxDynamicSharedMemorySize, FFT_SMEM);

    split_x_kernel<<<M_ * DM_ / 4 / 256, 256>>>(x, (unsigned*)xh, (unsigned*)xl);
    split_w_kernel<<<dim3(WN_ / 4 / 256, 4), 256>>>(Wq, Wk, Wv, Wo,
                                                    (unsigned*)wh, (unsigned*)wl);

    dim3 gg(M_ / 128, 4);
    gemm512<2><<<gg, 128>>>(xh, xl, wh,           wl,           bq, qp);
    gemm512<2><<<gg, 128>>>(xh, xl, wh + WN_,     wl + WN_,     bk, kp);
    gemm512<1><<<gg, 128>>>(xh, xl, wh + 2 * WN_, wl + 2 * WN_, bv, vp);
    fwd_corr_kernel<<<512, 512, FFT_SMEM>>>();
    inv_topk_kernel<<<64, 512, FFT_SMEM>>>();
    gather_kernel<<<dim3(256, 64), 256>>>();
    gemm512<0><<<gg, 128>>>(ch, cl, wh + 3 * WN_, wl + 3 * WN_, bo, out);
}

// round 15
// speedup vs baseline: 1.1958x; 1.1958x over previous
#include <cuda_runtime.h>
#include <cuda_bf16.h>
#include <cstdint>

#define B_    8
#define L_    4096
#define DM_   512
#define H_    8
#define D_    64
#define BH_   64
#define KTOP_ 8
#define M_    (B_ * L_)   // 32768
#define WN_   (DM_ * DM_) // 262144

// ---------------- scratch (device globals; no allocations allowed) ----------
__device__ __nv_bfloat16 gx_h[M_ * DM_];   // x hi/lo, [M,512]
__device__ __nv_bfloat16 gx_l[M_ * DM_];
__device__ __nv_bfloat16 gw_h[4 * WN_];    // Wq,Wk,Wv,Wo hi/lo, each [512,512]
__device__ __nv_bfloat16 gw_l[4 * WN_];
__device__ __nv_bfloat16 gc_h[M_ * DM_];   // ctx hi/lo, [M,512]
__device__ __nv_bfloat16 gc_l[M_ * DM_];
__device__ float  g_q[BH_ * D_ * L_];      // [bh][d][l]  (transposed)
__device__ float  g_k[BH_ * D_ * L_];
__device__ float  g_v[BH_ * L_ * D_];      // [bh][l][d]
__device__ float2 g_P[BH_ * 8 * L_];
__device__ float  g_w[BH_ * KTOP_];
__device__ int    g_i[BH_ * KTOP_];

// ---------------- bf16 pack/split helpers ------------------------------------
__device__ __forceinline__ unsigned pack2(float x, float y) {
    unsigned d;
    asm("cvt.rn.bf16x2.f32 %0, %1, %2;" : "=r"(d) : "f"(y), "f"(x));
    return d;   // lo half = bf16(x), hi half = bf16(y)
}
__device__ __forceinline__ void split2(float x, float y, unsigned& h, unsigned& l) {
    h = pack2(x, y);
    float hx = __uint_as_float(h << 16);
    float hy = __uint_as_float(h & 0xFFFF0000u);
    l = pack2(x - hx, y - hy);
}

// ---------------- split kernels -----------------------------------------------
__global__ void __launch_bounds__(256) split_x_kernel(const float* __restrict__ src,
                                                      unsigned* __restrict__ hi,
                                                      unsigned* __restrict__ lo) {
    const int i = blockIdx.x * 256 + threadIdx.x;   // float4 index
    float4 v = ((const float4*)src)[i];
    unsigned h01, l01, h23, l23;
    split2(v.x, v.y, h01, l01);
    split2(v.z, v.w, h23, l23);
    ((uint2*)hi)[i] = make_uint2(h01, h23);
    ((uint2*)lo)[i] = make_uint2(l01, l23);
}

// grid (256, 4): blockIdx.y selects weight matrix
__global__ void __launch_bounds__(256) split_w_kernel(const float* __restrict__ Wq,
                                                      const float* __restrict__ Wk,
                                                      const float* __restrict__ Wv,
                                                      const float* __restrict__ Wo,
                                                      unsigned* __restrict__ hi,
                                                      unsigned* __restrict__ lo) {
    const int sel = blockIdx.y;
    const float* src = sel == 0 ? Wq : (sel == 1 ? Wk : (sel == 2 ? Wv : Wo));
    const int i = blockIdx.x * 256 + threadIdx.x;
    float4 v = ((const float4*)src)[i];
    unsigned h01, l01, h23, l23;
    split2(v.x, v.y, h01, l01);
    split2(v.z, v.w, h23, l23);
    const int o = sel * (WN_ / 4) + i;
    ((uint2*)hi)[o] = make_uint2(h01, h23);
    ((uint2*)lo)[o] = make_uint2(l01, l23);
}

// Swizzled byte offset inside one 4KB sub-tile (128 rows x 32B).
__device__ __forceinline__ int swad(int r, int hf) {
    const int line = r >> 2;
    const int chunk = (((r & 3) * 2 + hf) ^ (line & 1));
    return line * 128 + chunk * 16;
}

__device__ __forceinline__ void cp16s(uint32_t saddr, const void* g) {
    asm volatile("cp.async.cg.shared.global [%0], [%1], 16;" :: "r"(saddr), "l"(g));
}

#define LDSM4(R, a)                                                           \
    asm volatile("ldmatrix.sync.aligned.m8n8.x4.shared.b16 {%0,%1,%2,%3}, [%4];" \
                 : "=r"((R)[0]), "=r"((R)[1]), "=r"((R)[2]), "=r"((R)[3])     \
                 : "r"(a))

#define MMA16(C, Ar, B0r, B1r)                                                \
    asm volatile(                                                             \
        "mma.sync.aligned.m16n8k16.row.col.f32.bf16.bf16.f32 "                \
        "{%0,%1,%2,%3},{%4,%5,%6,%7},{%8,%9},{%0,%1,%2,%3};"                  \
        : "+f"((C)[0]), "+f"((C)[1]), "+f"((C)[2]), "+f"((C)[3])              \
        : "r"((Ar)[0]), "r"((Ar)[1]), "r"((Ar)[2]), "r"((Ar)[3]),             \
          "r"(B0r), "r"(B1r))

// ---------------- GEMM: C[m,n] = sum_k A[m,k]*W[n,k] + bias[n] ---------------
// Pre-split 3xBF16; K-tile = 32 (two 16-col sub-tiles), 3-stage cp.async
// pipeline (32KB/stage, 96KB dynamic smem), ldmatrix, 32x64 warp tiles.
// Stage layout (offsets within stage block of 32KB):
//   Ah0 @0, Ah1 @4096, Al0 @8192, Al1 @12288,
//   Wh0 @16384, Wh1 @20480, Wl0 @24576, Wl1 @28672
// MODE 0: row-major [M,512]. MODE 1: [B,H,L,D]. MODE 2: [B,H,D,L].
template <int MODE>
__global__ void __launch_bounds__(256, 2) gemm512(const __nv_bfloat16* __restrict__ Ahp,
                                                  const __nv_bfloat16* __restrict__ Alp,
                                                  const __nv_bfloat16* __restrict__ Whp,
                                                  const __nv_bfloat16* __restrict__ Wlp,
                                                  const float* __restrict__ bias,
                                                  float* __restrict__ out) {
    extern __shared__ __align__(128) unsigned char gsm[];
    const uint32_t sb = (uint32_t)__cvta_generic_to_shared(gsm);

    const int tid  = threadIdx.x;
    const int bm   = blockIdx.x * 128;
    const int bn   = blockIdx.y * 128;
    const int warp = tid >> 5, lane = tid & 31;
    const int g  = lane >> 2, tg = lane & 3;
    const int wm = (warp >> 1) * 32;   // 4 warps along M
    const int wn = (warp & 1) * 64;    // 2 warps along N

    float c[2][8][4];
#pragma unroll
    for (int i = 0; i < 2; i++)
#pragma unroll
        for (int j = 0; j < 8; j++)
#pragma unroll
            for (int r = 0; r < 4; r++) c[i][j][r] = 0.f;

    // cp.async assignment: r = tid>>1 (0..127), hf = tid&1
    const int cr = tid >> 1, chf = tid & 1;
    const int sw = swad(cr, chf);
    const __nv_bfloat16* srcA_h = Ahp + (size_t)(bm + cr) * 512 + chf * 8;
    const __nv_bfloat16* srcA_l = Alp + (size_t)(bm + cr) * 512 + chf * 8;
    const __nv_bfloat16* srcW_h = Whp + (size_t)(bn + cr) * 512 + chf * 8;
    const __nv_bfloat16* srcW_l = Wlp + (size_t)(bn + cr) * 512 + chf * 8;

    // ldmatrix per-lane swizzled offsets (array-base-relative)
    const int lr = lane & 7, gI = lane >> 3;
    uint32_t aA[2], aW[4];
#pragma unroll
    for (int im = 0; im < 2; im++)
        aA[im] = sb + swad(wm + im * 16 + lr + (gI & 1) * 8, gI >> 1);
#pragma unroll
    for (int jp = 0; jp < 4; jp++)
        aW[jp] = sb + swad(wn + jp * 16 + lr + ((gI >> 1) & 1) * 8, gI & 1);

    auto cp_tile = [&](int stage, int kt32) {
        const uint32_t d = sb + stage * 32768 + sw;
#pragma unroll
        for (int s = 0; s < 2; s++) {
            const int k0 = kt32 * 32 + s * 16;
            const uint32_t ds = d + s * 4096;
            cp16s(ds,         srcA_h + k0);
            cp16s(ds + 8192,  srcA_l + k0);
            cp16s(ds + 16384, srcW_h + k0);
            cp16s(ds + 24576, srcW_l + k0);
        }
        asm volatile("cp.async.commit_group;" ::: "memory");
    };

    auto compute = [&](int stage) {
#pragma unroll
        for (int s = 0; s < 2; s++) {
            const uint32_t bo = stage * 32768 + s * 4096;
            unsigned ah[2][4], al[2][4];
            LDSM4(ah[0], aA[0] + bo);
            LDSM4(ah[1], aA[1] + bo);
            LDSM4(al[0], aA[0] + 8192 + bo);
            LDSM4(al[1], aA[1] + 8192 + bo);
#pragma unroll
            for (int jp2 = 0; jp2 < 2; jp2++) {
                unsigned wh[2][4], wl[2][4];
                LDSM4(wh[0], aW[2 * jp2] + 16384 + bo);
                LDSM4(wh[1], aW[2 * jp2 + 1] + 16384 + bo);
                LDSM4(wl[0], aW[2 * jp2] + 24576 + bo);
                LDSM4(wl[1], aW[2 * jp2 + 1] + 24576 + bo);
                const int jb = 4 * jp2;
                // pass 1 (hh)
#pragma unroll
                for (int p = 0; p < 2; p++) {
                    MMA16(c[0][jb + 2 * p],     ah[0], wh[p][0], wh[p][1]);
                    MMA16(c[1][jb + 2 * p],     ah[1], wh[p][0], wh[p][1]);
                    MMA16(c[0][jb + 2 * p + 1], ah[0], wh[p][2], wh[p][3]);
                    MMA16(c[1][jb + 2 * p + 1], ah[1], wh[p][2], wh[p][3]);
                }
                // pass 2 (hl)
#pragma unroll
                for (int p = 0; p < 2; p++) {
                    MMA16(c[0][jb + 2 * p],     ah[0], wl[p][0], wl[p][1]);
                    MMA16(c[1][jb + 2 * p],     ah[1], wl[p][0], wl[p][1]);
                    MMA16(c[0][jb + 2 * p + 1], ah[0], wl[p][2], wl[p][3]);
                    MMA16(c[1][jb + 2 * p + 1], ah[1], wl[p][2], wl[p][3]);
                }
                // pass 3 (lh)
#pragma unroll
                for (int p = 0; p < 2; p++) {
                    MMA16(c[0][jb + 2 * p],     al[0], wh[p][0], wh[p][1]);
                    MMA16(c[1][jb + 2 * p],     al[1], wh[p][0], wh[p][1]);
                    MMA16(c[0][jb + 2 * p + 1], al[0], wh[p][2], wh[p][3]);
                    MMA16(c[1][jb + 2 * p + 1], al[1], wh[p][2], wh[p][3]);
                }
            }
        }
    };

    cp_tile(0, 0);
    cp_tile(1, 1);
#pragma unroll 1
    for (int kt = 0; kt < 16; kt++) {
        const int stage = kt % 3;
        if (kt < 14) {
            asm volatile("cp.async.wait_group 1;" ::: "memory");
        } else {
            asm volatile("cp.async.wait_group 0;" ::: "memory");
        }
        __syncthreads();
        if (kt < 14) cp_tile((kt + 2) % 3, kt + 2);
        compute(stage);
    }

    // epilogue
#pragma unroll
    for (int im = 0; im < 2; im++) {
#pragma unroll
        for (int jn = 0; jn < 8; jn++) {
            const int mrow = bm + wm + im * 16 + g;
            const int ncol = bn + wn + jn * 8 + 2 * tg;
            const float bv0 = bias[ncol], bv1 = bias[ncol + 1];
            float v00 = c[im][jn][0] + bv0;
            float v01 = c[im][jn][1] + bv1;
            float v10 = c[im][jn][2] + bv0;
            float v11 = c[im][jn][3] + bv1;
            if (MODE == 0) {
                out[(size_t)mrow * 512 + ncol]           = v00;
                out[(size_t)mrow * 512 + ncol + 1]       = v01;
                out[(size_t)(mrow + 8) * 512 + ncol]     = v10;
                out[(size_t)(mrow + 8) * 512 + ncol + 1] = v11;
            } else if (MODE == 1) {
                const int h = ncol >> 6, d = ncol & 63;
                const int b = mrow >> 12, l = mrow & 4095;
                size_t base = (((size_t)(b * 8 + h)) * 4096 + l) * 64 + d;
                out[base]     = v00;
                out[base + 1] = v01;
                out[base + 8 * 64]     = v10;
                out[base + 8 * 64 + 1] = v11;
            } else {
                const int b = mrow >> 12, l = mrow & 4095;
                size_t base = ((size_t)(b * 512 + ncol)) * 4096 + l;
                out[base]        = v00;
                out[base + 4096] = v01;
                out[base + 8]        = v10;
                out[base + 4096 + 8] = v11;
            }
        }
    }
}

// ---------------- radix-8 Stockham FFT, 3 smem stages + register last stage ---
__device__ __forceinline__ float2 cmul(float2 a, float2 b) {
    return make_float2(a.x * b.x - a.y * b.y, a.x * b.y + a.y * b.x);
}
__device__ __forceinline__ float2 cadd(float2 a, float2 b) {
    return make_float2(a.x + b.x, a.y + b.y);
}
__device__ __forceinline__ float2 csub(float2 a, float2 b) {
    return make_float2(a.x - b.x, a.y - b.y);
}

__device__ __forceinline__ void bfly8(const float2* a, float2* z) {
    float2 t0 = cadd(a[0], a[4]), t1 = csub(a[0], a[4]);
    float2 t2 = cadd(a[2], a[6]), t3 = csub(a[2], a[6]);
    float2 E0 = cadd(t0, t2), E2 = csub(t0, t2);
    float2 E1 = make_float2(t1.x + t3.y, t1.y - t3.x);
    float2 E3 = make_float2(t1.x - t3.y, t1.y + t3.x);
    float2 u0 = cadd(a[1], a[5]), u1 = csub(a[1], a[5]);
    float2 u2 = cadd(a[3], a[7]), u3 = csub(a[3], a[7]);
    float2 O0 = cadd(u0, u2), O2 = csub(u0, u2);
    float2 O1 = make_float2(u1.x + u3.y, u1.y - u3.x);
    float2 O3 = make_float2(u1.x - u3.y, u1.y + u3.x);
    const float r = 0.70710678118654752f;
    float2 P1 = make_float2(r * (O1.x + O1.y), r * (O1.y - O1.x));
    float2 P2 = make_float2(O2.y, -O2.x);
    float2 P3 = make_float2(r * (O3.y - O3.x), -r * (O3.x + O3.y));
    z[0] = cadd(E0, O0); z[4] = csub(E0, O0);
    z[1] = cadd(E1, P1); z[5] = csub(E1, P1);
    z[2] = cadd(E2, P2); z[6] = csub(E2, P2);
    z[3] = cadd(E3, P3); z[7] = csub(E3, P3);
}

__device__ void fft4096r8_3(float2* x, float2* y, const float2* tw, int tid) {
    int ls = 0;
#pragma unroll 1
    for (int stage = 0; stage < 3; stage++) {
        const int s = 1 << ls;
        const int q = tid & (s - 1);
        const int sp = tid - q;
        float2 a[8], z[8];
#pragma unroll
        for (int j = 0; j < 8; j++) a[j] = x[tid + j * 512];
        bfly8(a, z);
        const int ob = 8 * tid - 7 * q;
        y[ob] = z[0];
#pragma unroll
        for (int j = 1; j < 8; j++) y[ob + j * s] = cmul(tw[j * sp], z[j]);
        __syncthreads();
        float2* tmp = x; x = y; y = tmp;
        ls += 3;
    }
}

__device__ __forceinline__ void fft_last(const float2* xin, float2* z, int tid) {
    float2 a[8];
#pragma unroll
    for (int j = 0; j < 8; j++) a[j] = xin[tid + j * 512];
    bfly8(a, z);
}

// ---------------- Phase A: packed FFT(q+ik), 8 d's per block, reduce ---------
__global__ void __launch_bounds__(512) fwd_corr_kernel() {
    extern __shared__ float2 sm[];
    float2* b0 = sm;
    float2* b1 = sm + 4096;
    float2* tw = sm + 8192;
    const int tid = threadIdx.x;
    for (int j = tid; j < 4096; j += 512) {
        float s, c;
        sincospif(-(float)j / 2048.0f, &s, &c);
        tw[j] = make_float2(c, s);
    }
    const int bh = blockIdx.x >> 3, grp = blockIdx.x & 7;
    const float* qb = g_q + ((size_t)bh * 64 + grp * 8) * 4096;
    const float* kb = g_k + ((size_t)bh * 64 + grp * 8) * 4096;

    float2 acc[8];
#pragma unroll
    for (int j = 0; j < 8; j++) acc[j] = make_float2(0.f, 0.f);

    for (int dd = 0; dd < 8; dd++) {
        const float* qp = qb + (size_t)dd * 4096;
        const float* kp = kb + (size_t)dd * 4096;
        __syncthreads();
#pragma unroll
        for (int j = 0; j < 8; j++) {
            int t = tid + j * 512;
            b0[t] = make_float2(qp[t], kp[t]);
        }
        __syncthreads();
        fft4096r8_3(b0, b1, tw, tid);
        float2 z[8];
        fft_last(b1, z, tid);
#pragma unroll
        for (int r = 0; r < 8; r++) b0[tid + r * 512] = z[r];
        __syncthreads();
#pragma unroll
        for (int j = 0; j < 8; j++) {
            const int f = tid + j * 512;
            float2 Z  = z[j];
            float2 Zm = b0[(4096 - f) & 4095];
            float Qr = 0.5f * (Z.x + Zm.x);
            float Qi = 0.5f * (Z.y - Zm.y);
            float Kr = 0.5f * (Z.y + Zm.y);
            float Ki = 0.5f * (Zm.x - Z.x);
            acc[j].x += Qr * Kr + Qi * Ki;
            acc[j].y += Qr * Ki - Qi * Kr;
        }
    }
    float2* Pout = g_P + (size_t)blockIdx.x * 4096;
#pragma unroll
    for (int j = 0; j < 8; j++) Pout[tid + j * 512] = acc[j];
}

// ---------------- Phase B fused: sum partials, FFT, top-8 + softmax ----------
__global__ void __launch_bounds__(512) inv_topk_kernel() {
    extern __shared__ float2 sm[];
    float2* b0 = sm;
    float2* b1 = sm + 4096;
    float2* tw = sm + 8192;
    const int tid = threadIdx.x;
    for (int j = tid; j < 4096; j += 512) {
        float s, c;
        sincospif(-(float)j / 2048.0f, &s, &c);
        tw[j] = make_float2(c, s);
    }
    const int bh = blockIdx.x;
    const float2* Pp = g_P + (size_t)bh * 8 * 4096;
    float2 acc[8];
#pragma unroll
    for (int j = 0; j < 8; j++) acc[j] = make_float2(0.f, 0.f);
    for (int grp = 0; grp < 8; grp++) {
#pragma unroll
        for (int j = 0; j < 8; j++) {
            float2 v = Pp[(size_t)grp * 4096 + tid + j * 512];
            acc[j].x += v.x;
            acc[j].y += v.y;
        }
    }
#pragma unroll
    for (int j = 0; j < 8; j++) b0[tid + j * 512] = acc[j];
    __syncthreads();
    fft4096r8_3(b0, b1, tw, tid);
    float2 z[8];
    fft_last(b1, z, tid);

    float* scr   = (float*)sm;
    float* svals = scr + 4096;
    int*   sidx  = (int*)(svals + 512);
    __shared__ int   chosen[KTOP_];
    __shared__ float chval[KTOP_];
    __syncthreads();
    const float sc = 1.0f / (4096.0f * 64.0f);
#pragma unroll
    for (int r = 0; r < 8; r++) scr[tid + r * 512] = z[r].x * sc;
    __syncthreads();

    for (int it = 0; it < KTOP_; it++) {
        float best = -3.0e38f;
        int bi = -1;
#pragma unroll
        for (int jj = 0; jj < 8; jj++) {
            const int t = tid + jj * 512;
            float v = scr[t];
            bool used = false;
            for (int u = 0; u < it; u++)
                if (chosen[u] == t) used = true;
            if (!used && (v > best || (v == best && t < bi))) { best = v; bi = t; }
        }
        svals[tid] = best;
        sidx[tid] = bi;
        __syncthreads();
        for (int off = 256; off > 0; off >>= 1) {
            if (tid < off) {
                if (svals[tid + off] > svals[tid] ||
                    (svals[tid + off] == svals[tid] && sidx[tid + off] < sidx[tid])) {
                    svals[tid] = svals[tid + off];
                    sidx[tid]  = sidx[tid + off];
                }
            }
            __syncthreads();
        }
        if (tid == 0) { chosen[it] = sidx[0]; chval[it] = svals[0]; }
        __syncthreads();
    }
    if (tid == 0) {
        float mx = chval[0];
        float e[KTOP_], se = 0.f;
        for (int u = 0; u < KTOP_; u++) { e[u] = expf(chval[u] - mx); se += e[u]; }
        float inv = 1.0f / se;
        for (int u = 0; u < KTOP_; u++) {
            g_w[bh * KTOP_ + u] = e[u] * inv;
            g_i[bh * KTOP_ + u] = chosen[u];
        }
    }
}

// ---------------- Phase D: gather V, write split bf16 ctx ---------------------
__global__ void __launch_bounds__(256) gather_kernel() {
    const int bh = blockIdx.y;
    const int b = bh >> 3, h = bh & 7;
    const int li = threadIdx.x >> 4;
    const int d4 = threadIdx.x & 15;
    const int l  = blockIdx.x * 16 + li;
    __shared__ float w[KTOP_];
    __shared__ int   ix[KTOP_];
    if (threadIdx.x < KTOP_) {
        w[threadIdx.x]  = g_w[bh * KTOP_ + threadIdx.x];
        ix[threadIdx.x] = g_i[bh * KTOP_ + threadIdx.x];
    }
    __syncthreads();
    const float4* vp = (const float4*)(g_v + (size_t)bh * L_ * D_);
    float4 acc = make_float4(0.f, 0.f, 0.f, 0.f);
#pragma unroll
    for (int u = 0; u < KTOP_; u++) {
        const int src = (l + ix[u]) & 4095;
        float4 v = vp[src * 16 + d4];
        const float wu = w[u];
        acc.x += wu * v.x;
        acc.y += wu * v.y;
        acc.z += wu * v.z;
        acc.w += wu * v.w;
    }
    unsigned h01, l01, h23, l23;
    split2(acc.x, acc.y, h01, l01);
    split2(acc.z, acc.w, h23, l23);
    const size_t e = (size_t)(b * L_ + l) * DM_ + h * 64 + d4 * 4;
    *(uint2*)((unsigned*)gc_h + (e >> 1)) = make_uint2(h01, h23);
    *(uint2*)((unsigned*)gc_l + (e >> 1)) = make_uint2(l01, l23);
}

// ---------------- launch ------------------------------------------------------
extern "C" void kernel_launch(void* const* d_in, const int* in_sizes, int n_in,
                              void* d_out, int out_size) {
    const float* x  = (const float*)d_in[0];
    const float* Wq = (const float*)d_in[1];
    const float* bq = (const float*)d_in[2];
    const float* Wk = (const float*)d_in[3];
    const float* bk = (const float*)d_in[4];
    const float* Wv = (const float*)d_in[5];
    const float* bv = (const float*)d_in[6];
    const float* Wo = (const float*)d_in[7];
    const float* bo = (const float*)d_in[8];
    float* out = (float*)d_out;

    float *qp, *kp, *vp;
    __nv_bfloat16 *xh, *xl, *wh, *wl, *ch, *cl;
    cudaGetSymbolAddress((void**)&qp, g_q);
    cudaGetSymbolAddress((void**)&kp, g_k);
    cudaGetSymbolAddress((void**)&vp, g_v);
    cudaGetSymbolAddress((void**)&xh, gx_h);
    cudaGetSymbolAddress((void**)&xl, gx_l);
    cudaGetSymbolAddress((void**)&wh, gw_h);
    cudaGetSymbolAddress((void**)&wl, gw_l);
    cudaGetSymbolAddress((void**)&ch, gc_h);
    cudaGetSymbolAddress((void**)&cl, gc_l);

    const int FFT_SMEM  = 98304;
    const int GEMM_SMEM = 98304;   // 3 stages x 32KB
    cudaFuncSetAttribute(gemm512<0>, cudaFuncAttributeMaxDynamicSharedMemorySize, GEMM_SMEM);
    cudaFuncSetAttribute(gemm512<1>, cudaFuncAttributeMaxDynamicSharedMemorySize, GEMM_SMEM);
    cudaFuncSetAttribute(gemm512<2>, cudaFuncAttributeMaxDynamicSharedMemorySize, GEMM_SMEM);
    cudaFuncSetAttribute(fwd_corr_kernel, cudaFuncAttributeMaxDynamicSharedMemorySize, FFT_SMEM);
    cudaFuncSetAttribute(inv_topk_kernel, cudaFuncAttributeMaxDynamicSharedMemorySize, FFT_SMEM);

    split_x_kernel<<<M_ * DM_ / 4 / 256, 256>>>(x, (unsigned*)xh, (unsigned*)xl);
    split_w_kernel<<<dim3(WN_ / 4 / 256, 4), 256>>>(Wq, Wk, Wv, Wo,
                                                    (unsigned*)wh, (unsigned*)wl);

    dim3 gg(M_ / 128, 4);
    gemm512<2><<<gg, 256, GEMM_SMEM>>>(xh, xl, wh,           wl,           bq, qp);
    gemm512<2><<<gg, 256, GEMM_SMEM>>>(xh, xl, wh + WN_,     wl + WN_,     bk, kp);
    gemm512<1><<<gg, 256, GEMM_SMEM>>>(xh, xl, wh + 2 * WN_, wl + 2 * WN_, bv, vp);
    fwd_corr_kernel<<<512, 512, FFT_SMEM>>>();
    inv_topk_kernel<<<64, 512, FFT_SMEM>>>();
    gather_kernel<<<dim3(256, 64), 256>>>();
    gemm512<0><<<gg, 256, GEMM_SMEM>>>(ch, cl, wh + 3 * WN_, wl + 3 * WN_, bo, out);
}

// round 16
// speedup vs baseline: 1.2942x; 1.0823x over previous
#include <cuda_runtime.h>
#include <cuda_bf16.h>
#include <cstdint>

#define B_    8
#define L_    4096
#define DM_   512
#define H_    8
#define D_    64
#define BH_   64
#define KTOP_ 8
#define M_    (B_ * L_)   // 32768
#define WN_   (DM_ * DM_) // 262144
#define SZ_   (BH_ * D_ * L_)  // 16777216 floats per Q/K/V tensor

// ---------------- scratch (device globals; no allocations allowed) ----------
__device__ float  g_qkv[3 * SZ_];     // q: [bh][d][l], k: [bh][d][l], v: [bh][l][d]
__device__ float  g_wqkv[3 * WN_];    // stacked Wq,Wk,Wv (fp32)
__device__ float  g_bqkv[3 * DM_];    // stacked bq,bk,bv
__device__ float2 g_P[BH_ * 8 * L_];
__device__ float  g_w[BH_ * KTOP_];
__device__ int    g_i[BH_ * KTOP_];
__device__ float  g_ctx[B_ * L_ * DM_];

// ---------------- bf16 pack/split helpers ------------------------------------
__device__ __forceinline__ unsigned pack2(float x, float y) {
    unsigned d;
    asm("cvt.rn.bf16x2.f32 %0, %1, %2;" : "=r"(d) : "f"(y), "f"(x));
    return d;   // lo half = bf16(x), hi half = bf16(y)
}
__device__ __forceinline__ void split2(float x, float y, unsigned& h, unsigned& l) {
    h = pack2(x, y);
    float hx = __uint_as_float(h << 16);
    float hy = __uint_as_float(h & 0xFFFF0000u);
    l = pack2(x - hx, y - hy);
}

// ---------------- stack kernel: Wq,Wk,Wv + biases into contiguous scratch ----
// grid (257, 3), 256 threads. Blocks 0..255 copy W float4 chunks; block 256
// copies the 512-entry bias.
__global__ void __launch_bounds__(256) stack_kernel(const float* __restrict__ Wq,
                                                    const float* __restrict__ Wk,
                                                    const float* __restrict__ Wv,
                                                    const float* __restrict__ bq,
                                                    const float* __restrict__ bk,
                                                    const float* __restrict__ bv) {
    const int sel = blockIdx.y;
    const float* Wsrc = sel == 0 ? Wq : (sel == 1 ? Wk : Wv);
    const float* bsrc = sel == 0 ? bq : (sel == 1 ? bk : bv);
    if (blockIdx.x < 256) {
        const int i = blockIdx.x * 256 + threadIdx.x;   // float4 index
        ((float4*)g_wqkv)[sel * (WN_ / 4) + i] = ((const float4*)Wsrc)[i];
    } else {
        for (int i = threadIdx.x; i < DM_; i += 256)
            g_bqkv[sel * DM_ + i] = bsrc[i];
    }
}

// Swizzled byte offset inside one 4KB k-tile buffer.
__device__ __forceinline__ int swad(int r, int hf) {
    const int line = r >> 2;
    const int chunk = (((r & 3) * 2 + hf) ^ (line & 1));
    return line * 128 + chunk * 16;
}

#define LDSM4(R, a)                                                           \
    asm volatile("ldmatrix.sync.aligned.m8n8.x4.shared.b16 {%0,%1,%2,%3}, [%4];" \
                 : "=r"((R)[0]), "=r"((R)[1]), "=r"((R)[2]), "=r"((R)[3])     \
                 : "r"(a))

#define MMA16(C, Ar, B0r, B1r)                                                \
    asm volatile(                                                             \
        "mma.sync.aligned.m16n8k16.row.col.f32.bf16.bf16.f32 "                \
        "{%0,%1,%2,%3},{%4,%5,%6,%7},{%8,%9},{%0,%1,%2,%3};"                  \
        : "+f"((C)[0]), "+f"((C)[1]), "+f"((C)[2]), "+f"((C)[3])              \
        : "r"((Ar)[0]), "r"((Ar)[1]), "r"((Ar)[2]), "r"((Ar)[3]),             \
          "r"(B0r), "r"(B1r))

// ================ GEMM core pieces (R10-proven: in-kernel 3xBF16 split) =====
// c[2][8][4] accumulators; 128x128 CTA tile; 8 warps (32x64 warp tiles);
// 2-buffer register-staged pipeline, ldmatrix fragment loads.

// ---------------- merged QKV GEMM ---------------------------------------------
// grid (256, 4, 3): sel = blockIdx.z in {Q,K,V}. All operand bases are device
// globals + sel*constant offsets (no runtime pointer selection).
__global__ void __launch_bounds__(256) gemm_qkv(const float* __restrict__ A) {
    __shared__ __align__(128) unsigned char gsm[32768];
    const uint32_t sb = (uint32_t)__cvta_generic_to_shared(gsm);

    const int tid  = threadIdx.x;
    const int bm   = blockIdx.x * 128;
    const int bn   = blockIdx.y * 128;
    const int sel  = blockIdx.z;
    const float* W    = g_wqkv + (size_t)sel * WN_;
    const float* bias = g_bqkv + sel * DM_;

    const int warp = tid >> 5, lane = tid & 31;
    const int g  = lane >> 2, tg = lane & 3;
    const int wm = (warp >> 1) * 32;
    const int wn = (warp & 1) * 64;

    float c[2][8][4];
#pragma unroll
    for (int i = 0; i < 2; i++)
#pragma unroll
        for (int j = 0; j < 8; j++)
#pragma unroll
            for (int r = 0; r < 4; r++) c[i][j][r] = 0.f;

    const int r0 = tid >> 2;
    const int c4 = (tid & 3) * 4;
    const int h_st = c4 >> 3;
    const int rel0 = swad(r0, h_st) + (c4 & 7) * 2;
    const int rel1 = swad(r0 + 64, h_st) + (c4 & 7) * 2;

    const int lr = lane & 7, gI = lane >> 3;
    uint32_t aA[2], aW[4];
#pragma unroll
    for (int im = 0; im < 2; im++)
        aA[im] = sb + swad(wm + im * 16 + lr + (gI & 1) * 8, gI >> 1);
#pragma unroll
    for (int jp = 0; jp < 4; jp++)
        aW[jp] = sb + 16384 + swad(wn + jp * 16 + lr + ((gI >> 1) & 1) * 8, gI & 1);

    auto load_tile = [&](int kt, float4& A0, float4& A1, float4& W0, float4& W1) {
        const int k0 = kt * 16;
        A0 = *(const float4*)&A[(size_t)(bm + r0) * 512 + k0 + c4];
        A1 = *(const float4*)&A[(size_t)(bm + r0 + 64) * 512 + k0 + c4];
        W0 = *(const float4*)&W[(size_t)(bn + r0) * 512 + k0 + c4];
        W1 = *(const float4*)&W[(size_t)(bn + r0 + 64) * 512 + k0 + c4];
    };
    auto store_pair = [&](int baseH, int off, float4 v) {
        unsigned h01, l01, h23, l23;
        split2(v.x, v.y, h01, l01);
        split2(v.z, v.w, h23, l23);
        *(uint2*)(gsm + baseH + off) = make_uint2(h01, h23);
        *(uint2*)(gsm + baseH + 8192 + off) = make_uint2(l01, l23);
    };
    auto store_tile = [&](int buf, float4 A0, float4 A1, float4 W0, float4 W1) {
        const int bo = buf * 4096;
        store_pair(0, bo + rel0, A0);
        store_pair(0, bo + rel1, A1);
        store_pair(16384, bo + rel0, W0);
        store_pair(16384, bo + rel1, W1);
    };
    auto compute = [&](int buf) {
        const uint32_t bo = buf * 4096;
        unsigned ah[2][4], al[2][4];
        LDSM4(ah[0], aA[0] + bo);
        LDSM4(ah[1], aA[1] + bo);
        LDSM4(al[0], aA[0] + 8192 + bo);
        LDSM4(al[1], aA[1] + 8192 + bo);
#pragma unroll
        for (int jp = 0; jp < 4; jp++) {
            unsigned wh[4], wl[4];
            LDSM4(wh, aW[jp] + bo);
            LDSM4(wl, aW[jp] + 8192 + bo);
#pragma unroll
            for (int im = 0; im < 2; im++) {
                MMA16(c[im][2 * jp],     ah[im], wh[0], wh[1]);
                MMA16(c[im][2 * jp],     ah[im], wl[0], wl[1]);
                MMA16(c[im][2 * jp],     al[im], wh[0], wh[1]);
                MMA16(c[im][2 * jp + 1], ah[im], wh[2], wh[3]);
                MMA16(c[im][2 * jp + 1], ah[im], wl[2], wl[3]);
                MMA16(c[im][2 * jp + 1], al[im], wh[2], wh[3]);
            }
        }
    };

    float4 a0, a1, w0, w1;
    load_tile(0, a0, a1, w0, w1);
    store_tile(0, a0, a1, w0, w1);
    __syncthreads();

    for (int kt = 0; kt < 32; kt++) {
        const int buf = kt & 1;
        float4 na0, na1, nw0, nw1;
        if (kt < 31) load_tile(kt + 1, na0, na1, nw0, nw1);
        compute(buf);
        if (kt < 31) store_tile(buf ^ 1, na0, na1, nw0, nw1);
        __syncthreads();
    }

    // epilogue: out base = g_qkv + sel*SZ_ (constant-offset indexing)
    float* outp = g_qkv + (size_t)sel * SZ_;
#pragma unroll
    for (int im = 0; im < 2; im++) {
#pragma unroll
        for (int jn = 0; jn < 8; jn++) {
            const int mrow = bm + wm + im * 16 + g;
            const int ncol = bn + wn + jn * 8 + 2 * tg;
            const float bv0 = bias[ncol], bv1 = bias[ncol + 1];
            float v00 = c[im][jn][0] + bv0;
            float v01 = c[im][jn][1] + bv1;
            float v10 = c[im][jn][2] + bv0;
            float v11 = c[im][jn][3] + bv1;
            const int b = mrow >> 12, l = mrow & 4095;
            if (sel == 2) {
                // V: [bh][l][d]
                const int h = ncol >> 6, d = ncol & 63;
                size_t base = (((size_t)(b * 8 + h)) * 4096 + l) * 64 + d;
                outp[base]     = v00;
                outp[base + 1] = v01;
                outp[base + 8 * 64]     = v10;     // l+8
                outp[base + 8 * 64 + 1] = v11;
            } else {
                // Q/K: [bh][d][l];  (b*8+h)*64+d == b*512 + ncol
                size_t base = ((size_t)(b * 512 + ncol)) * 4096 + l;
                outp[base]        = v00;
                outp[base + 4096] = v01;           // d+1
                outp[base + 8]        = v10;       // l+8
                outp[base + 4096 + 8] = v11;
            }
        }
    }
}

// ---------------- final GEMM: out = ctx @ Wo^T + bo (row-major) --------------
__global__ void __launch_bounds__(256) gemm_out(const float* __restrict__ A,
                                                const float* __restrict__ W,
                                                const float* __restrict__ bias,
                                                float* __restrict__ out) {
    __shared__ __align__(128) unsigned char gsm[32768];
    const uint32_t sb = (uint32_t)__cvta_generic_to_shared(gsm);

    const int tid  = threadIdx.x;
    const int bm   = blockIdx.x * 128;
    const int bn   = blockIdx.y * 128;
    const int warp = tid >> 5, lane = tid & 31;
    const int g  = lane >> 2, tg = lane & 3;
    const int wm = (warp >> 1) * 32;
    const int wn = (warp & 1) * 64;

    float c[2][8][4];
#pragma unroll
    for (int i = 0; i < 2; i++)
#pragma unroll
        for (int j = 0; j < 8; j++)
#pragma unroll
            for (int r = 0; r < 4; r++) c[i][j][r] = 0.f;

    const int r0 = tid >> 2;
    const int c4 = (tid & 3) * 4;
    const int h_st = c4 >> 3;
    const int rel0 = swad(r0, h_st) + (c4 & 7) * 2;
    const int rel1 = swad(r0 + 64, h_st) + (c4 & 7) * 2;

    const int lr = lane & 7, gI = lane >> 3;
    uint32_t aA[2], aW[4];
#pragma unroll
    for (int im = 0; im < 2; im++)
        aA[im] = sb + swad(wm + im * 16 + lr + (gI & 1) * 8, gI >> 1);
#pragma unroll
    for (int jp = 0; jp < 4; jp++)
        aW[jp] = sb + 16384 + swad(wn + jp * 16 + lr + ((gI >> 1) & 1) * 8, gI & 1);

    auto load_tile = [&](int kt, float4& A0, float4& A1, float4& W0, float4& W1) {
        const int k0 = kt * 16;
        A0 = *(const float4*)&A[(size_t)(bm + r0) * 512 + k0 + c4];
        A1 = *(const float4*)&A[(size_t)(bm + r0 + 64) * 512 + k0 + c4];
        W0 = *(const float4*)&W[(size_t)(bn + r0) * 512 + k0 + c4];
        W1 = *(const float4*)&W[(size_t)(bn + r0 + 64) * 512 + k0 + c4];
    };
    auto store_pair = [&](int baseH, int off, float4 v) {
        unsigned h01, l01, h23, l23;
        split2(v.x, v.y, h01, l01);
        split2(v.z, v.w, h23, l23);
        *(uint2*)(gsm + baseH + off) = make_uint2(h01, h23);
        *(uint2*)(gsm + baseH + 8192 + off) = make_uint2(l01, l23);
    };
    auto store_tile = [&](int buf, float4 A0, float4 A1, float4 W0, float4 W1) {
        const int bo = buf * 4096;
        store_pair(0, bo + rel0, A0);
        store_pair(0, bo + rel1, A1);
        store_pair(16384, bo + rel0, W0);
        store_pair(16384, bo + rel1, W1);
    };
    auto compute = [&](int buf) {
        const uint32_t bo = buf * 4096;
        unsigned ah[2][4], al[2][4];
        LDSM4(ah[0], aA[0] + bo);
        LDSM4(ah[1], aA[1] + bo);
        LDSM4(al[0], aA[0] + 8192 + bo);
        LDSM4(al[1], aA[1] + 8192 + bo);
#pragma unroll
        for (int jp = 0; jp < 4; jp++) {
            unsigned wh[4], wl[4];
            LDSM4(wh, aW[jp] + bo);
            LDSM4(wl, aW[jp] + 8192 + bo);
#pragma unroll
            for (int im = 0; im < 2; im++) {
                MMA16(c[im][2 * jp],     ah[im], wh[0], wh[1]);
                MMA16(c[im][2 * jp],     ah[im], wl[0], wl[1]);
                MMA16(c[im][2 * jp],     al[im], wh[0], wh[1]);
                MMA16(c[im][2 * jp + 1], ah[im], wh[2], wh[3]);
                MMA16(c[im][2 * jp + 1], ah[im], wl[2], wl[3]);
                MMA16(c[im][2 * jp + 1], al[im], wh[2], wh[3]);
            }
        }
    };

    float4 a0, a1, w0, w1;
    load_tile(0, a0, a1, w0, w1);
    store_tile(0, a0, a1, w0, w1);
    __syncthreads();

    for (int kt = 0; kt < 32; kt++) {
        const int buf = kt & 1;
        float4 na0, na1, nw0, nw1;
        if (kt < 31) load_tile(kt + 1, na0, na1, nw0, nw1);
        compute(buf);
        if (kt < 31) store_tile(buf ^ 1, na0, na1, nw0, nw1);
        __syncthreads();
    }

#pragma unroll
    for (int im = 0; im < 2; im++) {
#pragma unroll
        for (int jn = 0; jn < 8; jn++) {
            const int mrow = bm + wm + im * 16 + g;
            const int ncol = bn + wn + jn * 8 + 2 * tg;
            const float bv0 = bias[ncol], bv1 = bias[ncol + 1];
            out[(size_t)mrow * 512 + ncol]           = c[im][jn][0] + bv0;
            out[(size_t)mrow * 512 + ncol + 1]       = c[im][jn][1] + bv1;
            out[(size_t)(mrow + 8) * 512 + ncol]     = c[im][jn][2] + bv0;
            out[(size_t)(mrow + 8) * 512 + ncol + 1] = c[im][jn][3] + bv1;
        }
    }
}

// ---------------- radix-8 Stockham FFT, 3 smem stages + register last stage ---
__device__ __forceinline__ float2 cmul(float2 a, float2 b) {
    return make_float2(a.x * b.x - a.y * b.y, a.x * b.y + a.y * b.x);
}
__device__ __forceinline__ float2 cadd(float2 a, float2 b) {
    return make_float2(a.x + b.x, a.y + b.y);
}
__device__ __forceinline__ float2 csub(float2 a, float2 b) {
    return make_float2(a.x - b.x, a.y - b.y);
}

__device__ __forceinline__ void bfly8(const float2* a, float2* z) {
    float2 t0 = cadd(a[0], a[4]), t1 = csub(a[0], a[4]);
    float2 t2 = cadd(a[2], a[6]), t3 = csub(a[2], a[6]);
    float2 E0 = cadd(t0, t2), E2 = csub(t0, t2);
    float2 E1 = make_float2(t1.x + t3.y, t1.y - t3.x);
    float2 E3 = make_float2(t1.x - t3.y, t1.y + t3.x);
    float2 u0 = cadd(a[1], a[5]), u1 = csub(a[1], a[5]);
    float2 u2 = cadd(a[3], a[7]), u3 = csub(a[3], a[7]);
    float2 O0 = cadd(u0, u2), O2 = csub(u0, u2);
    float2 O1 = make_float2(u1.x + u3.y, u1.y - u3.x);
    float2 O3 = make_float2(u1.x - u3.y, u1.y + u3.x);
    const float r = 0.70710678118654752f;
    float2 P1 = make_float2(r * (O1.x + O1.y), r * (O1.y - O1.x));
    float2 P2 = make_float2(O2.y, -O2.x);
    float2 P3 = make_float2(r * (O3.y - O3.x), -r * (O3.x + O3.y));
    z[0] = cadd(E0, O0); z[4] = csub(E0, O0);
    z[1] = cadd(E1, P1); z[5] = csub(E1, P1);
    z[2] = cadd(E2, P2); z[6] = csub(E2, P2);
    z[3] = cadd(E3, P3); z[7] = csub(E3, P3);
}

__device__ void fft4096r8_3(float2* x, float2* y, const float2* tw, int tid) {
    int ls = 0;
#pragma unroll 1
    for (int stage = 0; stage < 3; stage++) {
        const int s = 1 << ls;
        const int q = tid & (s - 1);
        const int sp = tid - q;
        float2 a[8], z[8];
#pragma unroll
        for (int j = 0; j < 8; j++) a[j] = x[tid + j * 512];
        bfly8(a, z);
        const int ob = 8 * tid - 7 * q;
        y[ob] = z[0];
#pragma unroll
        for (int j = 1; j < 8; j++) y[ob + j * s] = cmul(tw[j * sp], z[j]);
        __syncthreads();
        float2* tmp = x; x = y; y = tmp;
        ls += 3;
    }
}

__device__ __forceinline__ void fft_last(const float2* xin, float2* z, int tid) {
    float2 a[8];
#pragma unroll
    for (int j = 0; j < 8; j++) a[j] = xin[tid + j * 512];
    bfly8(a, z);
}

// ---------------- Phase A: packed FFT(q+ik), 8 d's per block, reduce ---------
__global__ void __launch_bounds__(512) fwd_corr_kernel() {
    extern __shared__ float2 sm[];
    float2* b0 = sm;
    float2* b1 = sm + 4096;
    float2* tw = sm + 8192;
    const int tid = threadIdx.x;
    for (int j = tid; j < 4096; j += 512) {
        float s, c;
        sincospif(-(float)j / 2048.0f, &s, &c);
        tw[j] = make_float2(c, s);
    }
    const int bh = blockIdx.x >> 3, grp = blockIdx.x & 7;
    const float* qb = g_qkv + ((size_t)bh * 64 + grp * 8) * 4096;
    const float* kb = g_qkv + SZ_ + ((size_t)bh * 64 + grp * 8) * 4096;

    float2 acc[8];
#pragma unroll
    for (int j = 0; j < 8; j++) acc[j] = make_float2(0.f, 0.f);

    for (int dd = 0; dd < 8; dd++) {
        const float* qp = qb + (size_t)dd * 4096;
        const float* kp = kb + (size_t)dd * 4096;
        __syncthreads();
#pragma unroll
        for (int j = 0; j < 8; j++) {
            int t = tid + j * 512;
            b0[t] = make_float2(qp[t], kp[t]);
        }
        __syncthreads();
        fft4096r8_3(b0, b1, tw, tid);
        float2 z[8];
        fft_last(b1, z, tid);
#pragma unroll
        for (int r = 0; r < 8; r++) b0[tid + r * 512] = z[r];
        __syncthreads();
#pragma unroll
        for (int j = 0; j < 8; j++) {
            const int f = tid + j * 512;
            float2 Z  = z[j];
            float2 Zm = b0[(4096 - f) & 4095];
            float Qr = 0.5f * (Z.x + Zm.x);
            float Qi = 0.5f * (Z.y - Zm.y);
            float Kr = 0.5f * (Z.y + Zm.y);
            float Ki = 0.5f * (Zm.x - Z.x);
            acc[j].x += Qr * Kr + Qi * Ki;   // conj(Q)*K
            acc[j].y += Qr * Ki - Qi * Kr;
        }
    }
    float2* Pout = g_P + (size_t)blockIdx.x * 4096;
#pragma unroll
    for (int j = 0; j < 8; j++) Pout[tid + j * 512] = acc[j];
}

// ---------------- Phase B fused: sum partials, FFT, top-8 + softmax ----------
__global__ void __launch_bounds__(512) inv_topk_kernel() {
    extern __shared__ float2 sm[];
    float2* b0 = sm;
    float2* b1 = sm + 4096;
    float2* tw = sm + 8192;
    const int tid = threadIdx.x;
    for (int j = tid; j < 4096; j += 512) {
        float s, c;
        sincospif(-(float)j / 2048.0f, &s, &c);
        tw[j] = make_float2(c, s);
    }
    const int bh = blockIdx.x;
    const float2* Pp = g_P + (size_t)bh * 8 * 4096;
    float2 acc[8];
#pragma unroll
    for (int j = 0; j < 8; j++) acc[j] = make_float2(0.f, 0.f);
    for (int grp = 0; grp < 8; grp++) {
#pragma unroll
        for (int j = 0; j < 8; j++) {
            float2 v = Pp[(size_t)grp * 4096 + tid + j * 512];
            acc[j].x += v.x;
            acc[j].y += v.y;
        }
    }
#pragma unroll
    for (int j = 0; j < 8; j++) b0[tid + j * 512] = acc[j];
    __syncthreads();
    fft4096r8_3(b0, b1, tw, tid);
    float2 z[8];
    fft_last(b1, z, tid);

    // scratch: scr bytes 0..16K, svals 16K..18K, sidx 18K..20K (disjoint)
    float* scr   = (float*)sm;
    float* svals = scr + 4096;
    int*   sidx  = (int*)(svals + 512);
    __shared__ int   chosen[KTOP_];
    __shared__ float chval[KTOP_];
    __syncthreads();
    const float sc = 1.0f / (4096.0f * 64.0f);
#pragma unroll
    for (int r = 0; r < 8; r++) scr[tid + r * 512] = z[r].x * sc;
    __syncthreads();

    for (int it = 0; it < KTOP_; it++) {
        float best = -3.0e38f;
        int bi = -1;
#pragma unroll
        for (int jj = 0; jj < 8; jj++) {
            const int t = tid + jj * 512;
            float v = scr[t];
            bool used = false;
            for (int u = 0; u < it; u++)
                if (chosen[u] == t) used = true;
            if (!used && (v > best || (v == best && t < bi))) { best = v; bi = t; }
        }
        svals[tid] = best;
        sidx[tid] = bi;
        __syncthreads();
        for (int off = 256; off > 0; off >>= 1) {
            if (tid < off) {
                if (svals[tid + off] > svals[tid] ||
                    (svals[tid + off] == svals[tid] && sidx[tid + off] < sidx[tid])) {
                    svals[tid] = svals[tid + off];
                    sidx[tid]  = sidx[tid + off];
                }
            }
            __syncthreads();
        }
        if (tid == 0) { chosen[it] = sidx[0]; chval[it] = svals[0]; }
        __syncthreads();
    }
    if (tid == 0) {
        float mx = chval[0];
        float e[KTOP_], se = 0.f;
        for (int u = 0; u < KTOP_; u++) { e[u] = expf(chval[u] - mx); se += e[u]; }
        float inv = 1.0f / se;
        for (int u = 0; u < KTOP_; u++) {
            g_w[bh * KTOP_ + u] = e[u] * inv;
            g_i[bh * KTOP_ + u] = chosen[u];
        }
    }
}

// ---------------- Phase D: weighted circular gather of V (float4) ------------
__global__ void __launch_bounds__(256) gather_kernel() {
    const int bh = blockIdx.y;
    const int b = bh >> 3, h = bh & 7;
    const int li = threadIdx.x >> 4;     // 0..15
    const int d4 = threadIdx.x & 15;     // float4 lane
    const int l  = blockIdx.x * 16 + li;
    __shared__ float w[KTOP_];
    __shared__ int   ix[KTOP_];
    if (threadIdx.x < KTOP_) {
        w[threadIdx.x]  = g_w[bh * KTOP_ + threadIdx.x];
        ix[threadIdx.x] = g_i[bh * KTOP_ + threadIdx.x];
    }
    __syncthreads();
    const float4* vp = (const float4*)(g_qkv + 2 * (size_t)SZ_ + (size_t)bh * L_ * D_);
    float4 acc = make_float4(0.f, 0.f, 0.f, 0.f);
#pragma unroll
    for (int u = 0; u < KTOP_; u++) {
        const int src = (l + ix[u]) & 4095;
        float4 v = vp[src * 16 + d4];
        const float wu = w[u];
        acc.x += wu * v.x;
        acc.y += wu * v.y;
        acc.z += wu * v.z;
        acc.w += wu * v.w;
    }
    *(float4*)&g_ctx[((size_t)(b * L_ + l)) * DM_ + h * 64 + d4 * 4] = acc;
}

// ---------------- launch ------------------------------------------------------
extern "C" void kernel_launch(void* const* d_in, const int* in_sizes, int n_in,
                              void* d_out, int out_size) {
    const float* x  = (const float*)d_in[0];
    const float* Wq = (const float*)d_in[1];
    const float* bq = (const float*)d_in[2];
    const float* Wk = (const float*)d_in[3];
    const float* bk = (const float*)d_in[4];
    const float* Wv = (const float*)d_in[5];
    const float* bv = (const float*)d_in[6];
    const float* Wo = (const float*)d_in[7];
    const float* bo = (const float*)d_in[8];
    float* out = (float*)d_out;

    float* ctxp;
    cudaGetSymbolAddress((void**)&ctxp, g_ctx);

    const int FFT_SMEM = 98304;
    cudaFuncSetAttribute(fwd_corr_kernel, cudaFuncAttributeMaxDynamicSharedMemorySize, FFT_SMEM);
    cudaFuncSetAttribute(inv_topk_kernel, cudaFuncAttributeMaxDynamicSharedMemorySize, FFT_SMEM);

    stack_kernel<<<dim3(257, 3), 256>>>(Wq, Wk, Wv, bq, bk, bv);
    gemm_qkv<<<dim3(M_ / 128, 4, 3), 256>>>(x);
    fwd_corr_kernel<<<512, 512, FFT_SMEM>>>();
    inv_topk_kernel<<<64, 512, FFT_SMEM>>>();
    gather_kernel<<<dim3(256, 64), 256>>>();
    gemm_out<<<dim3(M_ / 128, 4), 256>>>(ctxp, Wo, bo, out);
}

// round 17
// speedup vs baseline: 1.3222x; 1.0217x over previous
#include <cuda_runtime.h>
#include <cuda_bf16.h>
#include <cstdint>

#define B_    8
#define L_    4096
#define DM_   512
#define H_    8
#define D_    64
#define BH_   64
#define KTOP_ 8
#define M_    (B_ * L_)   // 32768
#define WN_   (DM_ * DM_) // 262144
#define SZ_   (BH_ * D_ * L_)  // 16777216 floats per Q/K/V tensor

// ---------------- scratch (device globals; no allocations allowed) ----------
__device__ float  g_qkv[3 * SZ_];     // q: [bh][d][l], k: [bh][d][l], v: [bh][l][d]
__device__ float  g_wqkv[3 * WN_];    // stacked Wq,Wk,Wv (fp32)
__device__ float  g_bqkv[3 * DM_];    // stacked bq,bk,bv
__device__ float2 g_P[BH_ * 8 * L_];
__device__ float2 g_tw[L_];           // exp(-2*pi*i*j/4096)
__device__ float  g_w[BH_ * KTOP_];
__device__ int    g_i[BH_ * KTOP_];
__device__ float  g_ctx[B_ * L_ * DM_];

// ---------------- bf16 pack/split helpers ------------------------------------
__device__ __forceinline__ unsigned pack2(float x, float y) {
    unsigned d;
    asm("cvt.rn.bf16x2.f32 %0, %1, %2;" : "=r"(d) : "f"(y), "f"(x));
    return d;   // lo half = bf16(x), hi half = bf16(y)
}
__device__ __forceinline__ void split2(float x, float y, unsigned& h, unsigned& l) {
    h = pack2(x, y);
    float hx = __uint_as_float(h << 16);
    float hy = __uint_as_float(h & 0xFFFF0000u);
    l = pack2(x - hx, y - hy);
}

// ---------------- stack + twiddle init ----------------------------------------
__global__ void __launch_bounds__(256) stack_kernel(const float* __restrict__ Wq,
                                                    const float* __restrict__ Wk,
                                                    const float* __restrict__ Wv,
                                                    const float* __restrict__ bq,
                                                    const float* __restrict__ bk,
                                                    const float* __restrict__ bv) {
    const int sel = blockIdx.y;
    const float* Wsrc = sel == 0 ? Wq : (sel == 1 ? Wk : Wv);
    const float* bsrc = sel == 0 ? bq : (sel == 1 ? bk : bv);
    if (blockIdx.x < 256) {
        const int i = blockIdx.x * 256 + threadIdx.x;   // float4 index
        ((float4*)g_wqkv)[sel * (WN_ / 4) + i] = ((const float4*)Wsrc)[i];
    } else {
        for (int i = threadIdx.x; i < DM_; i += 256)
            g_bqkv[sel * DM_ + i] = bsrc[i];
    }
}

__global__ void __launch_bounds__(512) tw_init_kernel() {
    const int j = blockIdx.x * 512 + threadIdx.x;
    float s, c;
    sincospif(-(float)j / 2048.0f, &s, &c);
    g_tw[j] = make_float2(c, s);
}

// Swizzled byte offset inside one 4KB k-tile buffer.
__device__ __forceinline__ int swad(int r, int hf) {
    const int line = r >> 2;
    const int chunk = (((r & 3) * 2 + hf) ^ (line & 1));
    return line * 128 + chunk * 16;
}

#define LDSM4(R, a)                                                           \
    asm volatile("ldmatrix.sync.aligned.m8n8.x4.shared.b16 {%0,%1,%2,%3}, [%4];" \
                 : "=r"((R)[0]), "=r"((R)[1]), "=r"((R)[2]), "=r"((R)[3])     \
                 : "r"(a))

#define MMA16(C, Ar, B0r, B1r)                                                \
    asm volatile(                                                             \
        "mma.sync.aligned.m16n8k16.row.col.f32.bf16.bf16.f32 "                \
        "{%0,%1,%2,%3},{%4,%5,%6,%7},{%8,%9},{%0,%1,%2,%3};"                  \
        : "+f"((C)[0]), "+f"((C)[1]), "+f"((C)[2]), "+f"((C)[3])              \
        : "r"((Ar)[0]), "r"((Ar)[1]), "r"((Ar)[2]), "r"((Ar)[3]),             \
          "r"(B0r), "r"(B1r))

// ---------------- merged QKV GEMM ---------------------------------------------
// grid (256, 4, 3): sel = blockIdx.z in {Q,K,V}; fixed global bases + sel offs.
__global__ void __launch_bounds__(256) gemm_qkv(const float* __restrict__ A) {
    __shared__ __align__(128) unsigned char gsm[32768];
    const uint32_t sb = (uint32_t)__cvta_generic_to_shared(gsm);

    const int tid  = threadIdx.x;
    const int bm   = blockIdx.x * 128;
    const int bn   = blockIdx.y * 128;
    const int sel  = blockIdx.z;
    const float* W    = g_wqkv + (size_t)sel * WN_;
    const float* bias = g_bqkv + sel * DM_;

    const int warp = tid >> 5, lane = tid & 31;
    const int g  = lane >> 2, tg = lane & 3;
    const int wm = (warp >> 1) * 32;
    const int wn = (warp & 1) * 64;

    float c[2][8][4];
#pragma unroll
    for (int i = 0; i < 2; i++)
#pragma unroll
        for (int j = 0; j < 8; j++)
#pragma unroll
            for (int r = 0; r < 4; r++) c[i][j][r] = 0.f;

    const int r0 = tid >> 2;
    const int c4 = (tid & 3) * 4;
    const int h_st = c4 >> 3;
    const int rel0 = swad(r0, h_st) + (c4 & 7) * 2;
    const int rel1 = swad(r0 + 64, h_st) + (c4 & 7) * 2;

    const int lr = lane & 7, gI = lane >> 3;
    uint32_t aA[2], aW[4];
#pragma unroll
    for (int im = 0; im < 2; im++)
        aA[im] = sb + swad(wm + im * 16 + lr + (gI & 1) * 8, gI >> 1);
#pragma unroll
    for (int jp = 0; jp < 4; jp++)
        aW[jp] = sb + 16384 + swad(wn + jp * 16 + lr + ((gI >> 1) & 1) * 8, gI & 1);

    auto load_tile = [&](int kt, float4& A0, float4& A1, float4& W0, float4& W1) {
        const int k0 = kt * 16;
        A0 = *(const float4*)&A[(size_t)(bm + r0) * 512 + k0 + c4];
        A1 = *(const float4*)&A[(size_t)(bm + r0 + 64) * 512 + k0 + c4];
        W0 = *(const float4*)&W[(size_t)(bn + r0) * 512 + k0 + c4];
        W1 = *(const float4*)&W[(size_t)(bn + r0 + 64) * 512 + k0 + c4];
    };
    auto store_pair = [&](int baseH, int off, float4 v) {
        unsigned h01, l01, h23, l23;
        split2(v.x, v.y, h01, l01);
        split2(v.z, v.w, h23, l23);
        *(uint2*)(gsm + baseH + off) = make_uint2(h01, h23);
        *(uint2*)(gsm + baseH + 8192 + off) = make_uint2(l01, l23);
    };
    auto store_tile = [&](int buf, float4 A0, float4 A1, float4 W0, float4 W1) {
        const int bo = buf * 4096;
        store_pair(0, bo + rel0, A0);
        store_pair(0, bo + rel1, A1);
        store_pair(16384, bo + rel0, W0);
        store_pair(16384, bo + rel1, W1);
    };
    auto compute = [&](int buf) {
        const uint32_t bo = buf * 4096;
        unsigned ah[2][4], al[2][4];
        LDSM4(ah[0], aA[0] + bo);
        LDSM4(ah[1], aA[1] + bo);
        LDSM4(al[0], aA[0] + 8192 + bo);
        LDSM4(al[1], aA[1] + 8192 + bo);
#pragma unroll
        for (int jp = 0; jp < 4; jp++) {
            unsigned wh[4], wl[4];
            LDSM4(wh, aW[jp] + bo);
            LDSM4(wl, aW[jp] + 8192 + bo);
#pragma unroll
            for (int im = 0; im < 2; im++) {
                MMA16(c[im][2 * jp],     ah[im], wh[0], wh[1]);
                MMA16(c[im][2 * jp],     ah[im], wl[0], wl[1]);
                MMA16(c[im][2 * jp],     al[im], wh[0], wh[1]);
                MMA16(c[im][2 * jp + 1], ah[im], wh[2], wh[3]);
                MMA16(c[im][2 * jp + 1], ah[im], wl[2], wl[3]);
                MMA16(c[im][2 * jp + 1], al[im], wh[2], wh[3]);
            }
        }
    };

    float4 a0, a1, w0, w1;
    load_tile(0, a0, a1, w0, w1);
    store_tile(0, a0, a1, w0, w1);
    __syncthreads();

    for (int kt = 0; kt < 32; kt++) {
        const int buf = kt & 1;
        float4 na0, na1, nw0, nw1;
        if (kt < 31) load_tile(kt + 1, na0, na1, nw0, nw1);
        compute(buf);
        if (kt < 31) store_tile(buf ^ 1, na0, na1, nw0, nw1);
        __syncthreads();
    }

    float* outp = g_qkv + (size_t)sel * SZ_;
#pragma unroll
    for (int im = 0; im < 2; im++) {
#pragma unroll
        for (int jn = 0; jn < 8; jn++) {
            const int mrow = bm + wm + im * 16 + g;
            const int ncol = bn + wn + jn * 8 + 2 * tg;
            const float bv0 = bias[ncol], bv1 = bias[ncol + 1];
            float v00 = c[im][jn][0] + bv0;
            float v01 = c[im][jn][1] + bv1;
            float v10 = c[im][jn][2] + bv0;
            float v11 = c[im][jn][3] + bv1;
            const int b = mrow >> 12, l = mrow & 4095;
            if (sel == 2) {
                const int h = ncol >> 6, d = ncol & 63;
                size_t base = (((size_t)(b * 8 + h)) * 4096 + l) * 64 + d;
                outp[base]     = v00;
                outp[base + 1] = v01;
                outp[base + 8 * 64]     = v10;
                outp[base + 8 * 64 + 1] = v11;
            } else {
                size_t base = ((size_t)(b * 512 + ncol)) * 4096 + l;
                outp[base]        = v00;
                outp[base + 4096] = v01;
                outp[base + 8]        = v10;
                outp[base + 4096 + 8] = v11;
            }
        }
    }
}

// ---------------- final GEMM: out = ctx @ Wo^T + bo (row-major) --------------
__global__ void __launch_bounds__(256) gemm_out(const float* __restrict__ A,
                                                const float* __restrict__ W,
                                                const float* __restrict__ bias,
                                                float* __restrict__ out) {
    __shared__ __align__(128) unsigned char gsm[32768];
    const uint32_t sb = (uint32_t)__cvta_generic_to_shared(gsm);

    const int tid  = threadIdx.x;
    const int bm   = blockIdx.x * 128;
    const int bn   = blockIdx.y * 128;
    const int warp = tid >> 5, lane = tid & 31;
    const int g  = lane >> 2, tg = lane & 3;
    const int wm = (warp >> 1) * 32;
    const int wn = (warp & 1) * 64;

    float c[2][8][4];
#pragma unroll
    for (int i = 0; i < 2; i++)
#pragma unroll
        for (int j = 0; j < 8; j++)
#pragma unroll
            for (int r = 0; r < 4; r++) c[i][j][r] = 0.f;

    const int r0 = tid >> 2;
    const int c4 = (tid & 3) * 4;
    const int h_st = c4 >> 3;
    const int rel0 = swad(r0, h_st) + (c4 & 7) * 2;
    const int rel1 = swad(r0 + 64, h_st) + (c4 & 7) * 2;

    const int lr = lane & 7, gI = lane >> 3;
    uint32_t aA[2], aW[4];
#pragma unroll
    for (int im = 0; im < 2; im++)
        aA[im] = sb + swad(wm + im * 16 + lr + (gI & 1) * 8, gI >> 1);
#pragma unroll
    for (int jp = 0; jp < 4; jp++)
        aW[jp] = sb + 16384 + swad(wn + jp * 16 + lr + ((gI >> 1) & 1) * 8, gI & 1);

    auto load_tile = [&](int kt, float4& A0, float4& A1, float4& W0, float4& W1) {
        const int k0 = kt * 16;
        A0 = *(const float4*)&A[(size_t)(bm + r0) * 512 + k0 + c4];
        A1 = *(const float4*)&A[(size_t)(bm + r0 + 64) * 512 + k0 + c4];
        W0 = *(const float4*)&W[(size_t)(bn + r0) * 512 + k0 + c4];
        W1 = *(const float4*)&W[(size_t)(bn + r0 + 64) * 512 + k0 + c4];
    };
    auto store_pair = [&](int baseH, int off, float4 v) {
        unsigned h01, l01, h23, l23;
        split2(v.x, v.y, h01, l01);
        split2(v.z, v.w, h23, l23);
        *(uint2*)(gsm + baseH + off) = make_uint2(h01, h23);
        *(uint2*)(gsm + baseH + 8192 + off) = make_uint2(l01, l23);
    };
    auto store_tile = [&](int buf, float4 A0, float4 A1, float4 W0, float4 W1) {
        const int bo = buf * 4096;
        store_pair(0, bo + rel0, A0);
        store_pair(0, bo + rel1, A1);
        store_pair(16384, bo + rel0, W0);
        store_pair(16384, bo + rel1, W1);
    };
    auto compute = [&](int buf) {
        const uint32_t bo = buf * 4096;
        unsigned ah[2][4], al[2][4];
        LDSM4(ah[0], aA[0] + bo);
        LDSM4(ah[1], aA[1] + bo);
        LDSM4(al[0], aA[0] + 8192 + bo);
        LDSM4(al[1], aA[1] + 8192 + bo);
#pragma unroll
        for (int jp = 0; jp < 4; jp++) {
            unsigned wh[4], wl[4];
            LDSM4(wh, aW[jp] + bo);
            LDSM4(wl, aW[jp] + 8192 + bo);
#pragma unroll
            for (int im = 0; im < 2; im++) {
                MMA16(c[im][2 * jp],     ah[im], wh[0], wh[1]);
                MMA16(c[im][2 * jp],     ah[im], wl[0], wl[1]);
                MMA16(c[im][2 * jp],     al[im], wh[0], wh[1]);
                MMA16(c[im][2 * jp + 1], ah[im], wh[2], wh[3]);
                MMA16(c[im][2 * jp + 1], ah[im], wl[2], wl[3]);
                MMA16(c[im][2 * jp + 1], al[im], wh[2], wh[3]);
            }
        }
    };

    float4 a0, a1, w0, w1;
    load_tile(0, a0, a1, w0, w1);
    store_tile(0, a0, a1, w0, w1);
    __syncthreads();

    for (int kt = 0; kt < 32; kt++) {
        const int buf = kt & 1;
        float4 na0, na1, nw0, nw1;
        if (kt < 31) load_tile(kt + 1, na0, na1, nw0, nw1);
        compute(buf);
        if (kt < 31) store_tile(buf ^ 1, na0, na1, nw0, nw1);
        __syncthreads();
    }

#pragma unroll
    for (int im = 0; im < 2; im++) {
#pragma unroll
        for (int jn = 0; jn < 8; jn++) {
            const int mrow = bm + wm + im * 16 + g;
            const int ncol = bn + wn + jn * 8 + 2 * tg;
            const float bv0 = bias[ncol], bv1 = bias[ncol + 1];
            out[(size_t)mrow * 512 + ncol]           = c[im][jn][0] + bv0;
            out[(size_t)mrow * 512 + ncol + 1]       = c[im][jn][1] + bv1;
            out[(size_t)(mrow + 8) * 512 + ncol]     = c[im][jn][2] + bv0;
            out[(size_t)(mrow + 8) * 512 + ncol + 1] = c[im][jn][3] + bv1;
        }
    }
}

// ---------------- radix-8 Stockham FFT, 3 smem stages + register last stage ---
__device__ __forceinline__ float2 cmul(float2 a, float2 b) {
    return make_float2(a.x * b.x - a.y * b.y, a.x * b.y + a.y * b.x);
}
__device__ __forceinline__ float2 cadd(float2 a, float2 b) {
    return make_float2(a.x + b.x, a.y + b.y);
}
__device__ __forceinline__ float2 csub(float2 a, float2 b) {
    return make_float2(a.x - b.x, a.y - b.y);
}

__device__ __forceinline__ void bfly8(const float2* a, float2* z) {
    float2 t0 = cadd(a[0], a[4]), t1 = csub(a[0], a[4]);
    float2 t2 = cadd(a[2], a[6]), t3 = csub(a[2], a[6]);
    float2 E0 = cadd(t0, t2), E2 = csub(t0, t2);
    float2 E1 = make_float2(t1.x + t3.y, t1.y - t3.x);
    float2 E3 = make_float2(t1.x - t3.y, t1.y + t3.x);
    float2 u0 = cadd(a[1], a[5]), u1 = csub(a[1], a[5]);
    float2 u2 = cadd(a[3], a[7]), u3 = csub(a[3], a[7]);
    float2 O0 = cadd(u0, u2), O2 = csub(u0, u2);
    float2 O1 = make_float2(u1.x + u3.y, u1.y - u3.x);
    float2 O3 = make_float2(u1.x - u3.y, u1.y + u3.x);
    const float r = 0.70710678118654752f;
    float2 P1 = make_float2(r * (O1.x + O1.y), r * (O1.y - O1.x));
    float2 P2 = make_float2(O2.y, -O2.x);
    float2 P3 = make_float2(r * (O3.y - O3.x), -r * (O3.x + O3.y));
    z[0] = cadd(E0, O0); z[4] = csub(E0, O0);
    z[1] = cadd(E1, P1); z[5] = csub(E1, P1);
    z[2] = cadd(E2, P2); z[6] = csub(E2, P2);
    z[3] = cadd(E3, P3); z[7] = csub(E3, P3);
}

__device__ void fft4096r8_3(float2* x, float2* y, const float2* tw, int tid) {
    int ls = 0;
#pragma unroll 1
    for (int stage = 0; stage < 3; stage++) {
        const int s = 1 << ls;
        const int q = tid & (s - 1);
        const int sp = tid - q;
        float2 a[8], z[8];
#pragma unroll
        for (int j = 0; j < 8; j++) a[j] = x[tid + j * 512];
        bfly8(a, z);
        const int ob = 8 * tid - 7 * q;
        y[ob] = z[0];
#pragma unroll
        for (int j = 1; j < 8; j++) y[ob + j * s] = cmul(tw[j * sp], z[j]);
        __syncthreads();
        float2* tmp = x; x = y; y = tmp;
        ls += 3;
    }
}

__device__ __forceinline__ void fft_last(const float2* xin, float2* z, int tid) {
    float2 a[8];
#pragma unroll
    for (int j = 0; j < 8; j++) a[j] = xin[tid + j * 512];
    bfly8(a, z);
}

// load twiddle table from gmem (bit-identical values, no MUFU burst)
__device__ __forceinline__ void load_tw(float2* tw, int tid) {
    const float4* src = (const float4*)g_tw;
    float4* dst = (float4*)tw;
#pragma unroll
    for (int j = 0; j < 4; j++) dst[tid + j * 512] = src[tid + j * 512];
}

// ---------------- Phase A: packed FFT(q+ik), 8 d's per block, reduce ---------
__global__ void __launch_bounds__(512) fwd_corr_kernel() {
    extern __shared__ float2 sm[];
    float2* b0 = sm;
    float2* b1 = sm + 4096;
    float2* tw = sm + 8192;
    const int tid = threadIdx.x;
    load_tw(tw, tid);
    const int bh = blockIdx.x >> 3, grp = blockIdx.x & 7;
    const float* qb = g_qkv + ((size_t)bh * 64 + grp * 8) * 4096;
    const float* kb = g_qkv + SZ_ + ((size_t)bh * 64 + grp * 8) * 4096;

    float2 acc[8];
#pragma unroll
    for (int j = 0; j < 8; j++) acc[j] = make_float2(0.f, 0.f);

    for (int dd = 0; dd < 8; dd++) {
        const float* qp = qb + (size_t)dd * 4096;
        const float* kp = kb + (size_t)dd * 4096;
        __syncthreads();
#pragma unroll
        for (int j = 0; j < 8; j++) {
            int t = tid + j * 512;
            b0[t] = make_float2(qp[t], kp[t]);
        }
        __syncthreads();
        fft4096r8_3(b0, b1, tw, tid);
        float2 z[8];
        fft_last(b1, z, tid);
#pragma unroll
        for (int r = 0; r < 8; r++) b0[tid + r * 512] = z[r];
        __syncthreads();
#pragma unroll
        for (int j = 0; j < 8; j++) {
            const int f = tid + j * 512;
            float2 Z  = z[j];
            float2 Zm = b0[(4096 - f) & 4095];
            float Qr = 0.5f * (Z.x + Zm.x);
            float Qi = 0.5f * (Z.y - Zm.y);
            float Kr = 0.5f * (Z.y + Zm.y);
            float Ki = 0.5f * (Zm.x - Z.x);
            acc[j].x += Qr * Kr + Qi * Ki;   // conj(Q)*K
            acc[j].y += Qr * Ki - Qi * Kr;
        }
    }
    float2* Pout = g_P + (size_t)blockIdx.x * 4096;
#pragma unroll
    for (int j = 0; j < 8; j++) Pout[tid + j * 512] = acc[j];
}

// ---------------- Phase B fused: sum partials, FFT, top-8 + softmax ----------
__global__ void __launch_bounds__(512) inv_topk_kernel() {
    extern __shared__ float2 sm[];
    float2* b0 = sm;
    float2* b1 = sm + 4096;
    float2* tw = sm + 8192;
    const int tid = threadIdx.x;
    const int lane = tid & 31, wid = tid >> 5;
    load_tw(tw, tid);
    const int bh = blockIdx.x;
    const float2* Pp = g_P + (size_t)bh * 8 * 4096;
    float2 acc[8];
#pragma unroll
    for (int j = 0; j < 8; j++) acc[j] = make_float2(0.f, 0.f);
    for (int grp = 0; grp < 8; grp++) {
#pragma unroll
        for (int j = 0; j < 8; j++) {
            float2 v = Pp[(size_t)grp * 4096 + tid + j * 512];
            acc[j].x += v.x;
            acc[j].y += v.y;
        }
    }
#pragma unroll
    for (int j = 0; j < 8; j++) b0[tid + j * 512] = acc[j];
    __syncthreads();
    fft4096r8_3(b0, b1, tw, tid);
    float2 z[8];
    fft_last(b1, z, tid);

    // corr values stay in registers: v[r] = corr[tid + 512r]
    const float sc = 1.0f / (4096.0f * 64.0f);
    float v[8];
#pragma unroll
    for (int r = 0; r < 8; r++) v[r] = z[r].x * sc;

    __shared__ float swv[16];
    __shared__ int   swi[16];
    __shared__ int   chosen[KTOP_];
    __shared__ float chval[KTOP_];

#pragma unroll 1
    for (int it = 0; it < KTOP_; it++) {
        // local max over 8 register values (idx = tid + 512r, increasing in r:
        // strict > keeps the lowest index on ties)
        float best = v[0];
        int br = 0;
#pragma unroll
        for (int r = 1; r < 8; r++)
            if (v[r] > best) { best = v[r]; br = r; }
        int bi = tid + (br << 9);
        // warp shuffle reduce (prefer higher val, then lower idx)
#pragma unroll
        for (int off = 16; off > 0; off >>= 1) {
            float ov = __shfl_down_sync(0xFFFFFFFFu, best, off);
            int   oi = __shfl_down_sync(0xFFFFFFFFu, bi, off);
            if (ov > best || (ov == best && oi < bi)) { best = ov; bi = oi; }
        }
        if (lane == 0) { swv[wid] = best; swi[wid] = bi; }
        __syncthreads();
        if (tid < 32) {
            float bv2 = (tid < 16) ? swv[tid] : -3.0e38f;
            int   bi2 = (tid < 16) ? swi[tid] : 0x7FFFFFFF;
#pragma unroll
            for (int off = 8; off > 0; off >>= 1) {
                float ov = __shfl_down_sync(0xFFFFFFFFu, bv2, off);
                int   oi = __shfl_down_sync(0xFFFFFFFFu, bi2, off);
                if (ov > bv2 || (ov == bv2 && oi < bi2)) { bv2 = ov; bi2 = oi; }
            }
            if (tid == 0) { chosen[it] = bi2; chval[it] = bv2; }
        }
        __syncthreads();
        const int ch = chosen[it];
        if ((ch & 511) == tid) v[ch >> 9] = -3.0e38f;   // mark used (register)
    }
    if (tid == 0) {
        float mx = chval[0];
        float e[KTOP_], se = 0.f;
        for (int u = 0; u < KTOP_; u++) { e[u] = expf(chval[u] - mx); se += e[u]; }
        float inv = 1.0f / se;
        for (int u = 0; u < KTOP_; u++) {
            g_w[bh * KTOP_ + u] = e[u] * inv;
            g_i[bh * KTOP_ + u] = chosen[u];
        }
    }
}

// ---------------- Phase D: weighted circular gather of V (float4) ------------
__global__ void __launch_bounds__(256) gather_kernel() {
    const int bh = blockIdx.y;
    const int b = bh >> 3, h = bh & 7;
    const int li = threadIdx.x >> 4;     // 0..15
    const int d4 = threadIdx.x & 15;     // float4 lane
    const int l  = blockIdx.x * 16 + li;
    __shared__ float w[KTOP_];
    __shared__ int   ix[KTOP_];
    if (threadIdx.x < KTOP_) {
        w[threadIdx.x]  = g_w[bh * KTOP_ + threadIdx.x];
        ix[threadIdx.x] = g_i[bh * KTOP_ + threadIdx.x];
    }
    __syncthreads();
    const float4* vp = (const float4*)(g_qkv + 2 * (size_t)SZ_ + (size_t)bh * L_ * D_);
    float4 acc = make_float4(0.f, 0.f, 0.f, 0.f);
#pragma unroll
    for (int u = 0; u < KTOP_; u++) {
        const int src = (l + ix[u]) & 4095;
        float4 v = vp[src * 16 + d4];
        const float wu = w[u];
        acc.x += wu * v.x;
        acc.y += wu * v.y;
        acc.z += wu * v.z;
        acc.w += wu * v.w;
    }
    *(float4*)&g_ctx[((size_t)(b * L_ + l)) * DM_ + h * 64 + d4 * 4] = acc;
}

// ---------------- launch ------------------------------------------------------
extern "C" void kernel_launch(void* const* d_in, const int* in_sizes, int n_in,
                              void* d_out, int out_size) {
    const float* x  = (const float*)d_in[0];
    const float* Wq = (const float*)d_in[1];
    const float* bq = (const float*)d_in[2];
    const float* Wk = (const float*)d_in[3];
    const float* bk = (const float*)d_in[4];
    const float* Wv = (const float*)d_in[5];
    const float* bv = (const float*)d_in[6];
    const float* Wo = (const float*)d_in[7];
    const float* bo = (const float*)d_in[8];
    float* out = (float*)d_out;

    float* ctxp;
    cudaGetSymbolAddress((void**)&ctxp, g_ctx);

    const int FFT_SMEM = 98304;
    cudaFuncSetAttribute(fwd_corr_kernel, cudaFuncAttributeMaxDynamicSharedMemorySize, FFT_SMEM);
    cudaFuncSetAttribute(inv_topk_kernel, cudaFuncAttributeMaxDynamicSharedMemorySize, FFT_SMEM);

    tw_init_kernel<<<8, 512>>>();
    stack_kernel<<<dim3(257, 3), 256>>>(Wq, Wk, Wv, bq, bk, bv);
    gemm_qkv<<<dim3(M_ / 128, 4, 3), 256>>>(x);
    fwd_corr_kernel<<<512, 512, FFT_SMEM>>>();
    inv_topk_kernel<<<64, 512, FFT_SMEM>>>();
    gather_kernel<<<dim3(256, 64), 256>>>();
    gemm_out<<<dim3(M_ / 128, 4), 256>>>(ctxp, Wo, bo, out);
}